// round 1
// baseline (speedup 1.0000x reference)
#include <cuda_runtime.h>
#include <math.h>

#define Bn   16
#define Cn   512
#define HWn  576
#define CMn  (Cn*HWn)     // 294912
#define NTOT (Bn*HWn)     // 9216

// ---------------- device scratch (no allocs allowed) ----------------
__device__ float g_q[Bn*CMn];        // q projection, (B, C, HW) layout
__device__ float g_k[Bn*CMn];        // k projection, (B, C, HW) layout
__device__ float g_colmax[NTOT*Bn];  // per-(n, bk) max over m
__device__ float g_invnrm[NTOT];     // 1/max(||x5[:,p]||, 1e-12)
__device__ float g_seeds[Bn*Cn];
__device__ float g_corr[NTOT];
__device__ float g_cormap[NTOT];
__device__ float g_proto[Cn];

// ---------------------------------------------------------------
// GEMM: Y[b,o,m] = sum_c W[o,c]*X[b,c,m] + bias[o] (+ X[b,o,m] if RES)
// Tiles: 64(o) x 64(m), K-chunk 16. Block 256 threads, 4x4 per thread.
// DST: 0 -> Yp param, 1 -> g_q, 2 -> g_k
// ---------------------------------------------------------------
template<bool RES, int DST>
__global__ void __launch_bounds__(256) conv_gemm(const float* __restrict__ Wm,
                                                 const float* __restrict__ X,
                                                 const float* __restrict__ bias,
                                                 float* __restrict__ Yp)
{
    __shared__ __align__(16) float Ws[16][68];   // [c][o] (transposed on store)
    __shared__ __align__(16) float Xs[16][68];   // [c][m]
    const int m0 = blockIdx.x * 64;
    const int o0 = blockIdx.y * 64;
    const int b  = blockIdx.z;
    const float* Xb = X + (size_t)b * CMn;
    const int t  = threadIdx.x;
    const int tx = t & 15, ty = t >> 4;

    float acc[4][4] = {};

    for (int c0 = 0; c0 < Cn; c0 += 16) {
        // load W tile (64 o x 16 c), transpose to Ws[c][o]
        {
            const int ow = t >> 2;            // 0..63
            const int cv = (t & 3) * 4;       // 0,4,8,12
            float4 w4 = *(const float4*)(Wm + (size_t)(o0 + ow) * Cn + c0 + cv);
            Ws[cv + 0][ow] = w4.x;
            Ws[cv + 1][ow] = w4.y;
            Ws[cv + 2][ow] = w4.z;
            Ws[cv + 3][ow] = w4.w;
        }
        // load X tile (16 c x 64 m) directly
        {
            const int cx = t >> 4;            // 0..15
            const int mv = (t & 15) * 4;      // 0..60
            *(float4*)&Xs[cx][mv] =
                *(const float4*)(Xb + (size_t)(c0 + cx) * HWn + m0 + mv);
        }
        __syncthreads();
        #pragma unroll
        for (int kk = 0; kk < 16; kk++) {
            float4 a4 = *(const float4*)&Ws[kk][ty * 4];
            float4 x4 = *(const float4*)&Xs[kk][tx * 4];
            float av[4] = {a4.x, a4.y, a4.z, a4.w};
            float xv[4] = {x4.x, x4.y, x4.z, x4.w};
            #pragma unroll
            for (int i = 0; i < 4; i++)
                #pragma unroll
                for (int j = 0; j < 4; j++)
                    acc[i][j] += av[i] * xv[j];
        }
        __syncthreads();
    }

    float* Y = (DST == 1) ? g_q : (DST == 2) ? g_k : Yp;
    #pragma unroll
    for (int i = 0; i < 4; i++) {
        const int o = o0 + ty * 4 + i;
        const int m = m0 + tx * 4;
        const float bb = bias[o];
        float4 r;
        r.x = acc[i][0] + bb;
        r.y = acc[i][1] + bb;
        r.z = acc[i][2] + bb;
        r.w = acc[i][3] + bb;
        if (RES) {
            float4 xr = *(const float4*)(X + (size_t)b * CMn + (size_t)o * HWn + m);
            r.x += xr.x; r.y += xr.y; r.z += xr.z; r.w += xr.w;
        }
        *(float4*)(Y + (size_t)b * CMn + (size_t)o * HWn + m) = r;
    }
}

// ---------------------------------------------------------------
// Scores: for each n = bq*HW + mq, each bk: max over m of q[n]·k[bk,:,m].
// (1/sqrt(C) scale and softmax are monotonic -> skipped; only the argmax
//  mask downstream consumes these values.)
// Block: 64 mq rows x one (bq, bk) pair; loops 9 mk-tiles of 64 internally.
// ---------------------------------------------------------------
__global__ void __launch_bounds__(256) scores_kernel()
{
    __shared__ __align__(16) float Qs[16][68];
    __shared__ __align__(16) float Ks[16][68];
    __shared__ float red[64][17];

    const int mq0 = blockIdx.x * 64;
    const int bq  = blockIdx.y;
    const int bk  = blockIdx.z;
    const float* Qb = g_q + (size_t)bq * CMn;
    const float* Kb = g_k + (size_t)bk * CMn;

    const int t  = threadIdx.x;
    const int tx = t & 15, ty = t >> 4;
    const int cl = t >> 4;
    const int mv = (t & 15) * 4;

    float rowmax[4] = {-1e30f, -1e30f, -1e30f, -1e30f};

    for (int mk0 = 0; mk0 < HWn; mk0 += 64) {
        float acc[4][4] = {};
        for (int c0 = 0; c0 < Cn; c0 += 16) {
            *(float4*)&Qs[cl][mv] =
                *(const float4*)(Qb + (size_t)(c0 + cl) * HWn + mq0 + mv);
            *(float4*)&Ks[cl][mv] =
                *(const float4*)(Kb + (size_t)(c0 + cl) * HWn + mk0 + mv);
            __syncthreads();
            #pragma unroll
            for (int kk = 0; kk < 16; kk++) {
                float4 a4 = *(const float4*)&Qs[kk][ty * 4];
                float4 x4 = *(const float4*)&Ks[kk][tx * 4];
                float av[4] = {a4.x, a4.y, a4.z, a4.w};
                float xv[4] = {x4.x, x4.y, x4.z, x4.w};
                #pragma unroll
                for (int i = 0; i < 4; i++)
                    #pragma unroll
                    for (int j = 0; j < 4; j++)
                        acc[i][j] += av[i] * xv[j];
            }
            __syncthreads();
        }
        #pragma unroll
        for (int i = 0; i < 4; i++) {
            float m = fmaxf(fmaxf(acc[i][0], acc[i][1]),
                            fmaxf(acc[i][2], acc[i][3]));
            rowmax[i] = fmaxf(rowmax[i], m);
        }
    }

    #pragma unroll
    for (int i = 0; i < 4; i++)
        red[ty * 4 + i][tx] = rowmax[i];
    __syncthreads();
    if (t < 64) {
        float m = red[t][0];
        #pragma unroll
        for (int j = 1; j < 16; j++) m = fmaxf(m, red[t][j]);
        g_colmax[(size_t)(bq * HWn + mq0 + t) * Bn + bk] = m;
    }
}

// ---------------------------------------------------------------
// x_w(n) = sum_bk colmax (monotonic stand-in for mean+softmax);
// mask = (x_w == per-image max). One block per image, 576 threads.
// ---------------------------------------------------------------
__global__ void xw_mask_kernel(float* __restrict__ o_mask)
{
    __shared__ float smax[HWn];
    const int b = blockIdx.x, p = threadIdx.x;
    const float* cm = g_colmax + (size_t)(b * HWn + p) * Bn;
    float s = 0.f;
    #pragma unroll
    for (int j = 0; j < Bn; j++) s += cm[j];
    smax[p] = s;
    __syncthreads();
    for (int st = 512; st > 0; st >>= 1) {
        if (p < st && p + st < HWn) smax[p] = fmaxf(smax[p], smax[p + st]);
        __syncthreads();
    }
    o_mask[b * HWn + p] = (s == smax[0]) ? 1.0f : 0.0f;
}

// per-position inverse channel L2 norm of x5new
__global__ void invnrm_kernel(const float* __restrict__ x5n)
{
    const int n = blockIdx.x * blockDim.x + threadIdx.x;  // < 9216
    const int b = n / HWn, p = n - b * HWn;
    const float* xp = x5n + (size_t)b * CMn + p;
    float s = 0.f;
    for (int c = 0; c < Cn; c++) {
        float v = xp[(size_t)c * HWn];
        s += v * v;
    }
    g_invnrm[n] = 1.0f / fmaxf(sqrtf(s), 1e-12f);
}

// seeds[b,c] = sum over masked positions of norm0[b,c,p]
__global__ void seeds_kernel(const float* __restrict__ x5n,
                             const float* __restrict__ mask)
{
    __shared__ int cnt;
    __shared__ int plist[HWn];
    const int b = blockIdx.x, c = threadIdx.x;  // blockDim = 512
    if (c == 0) cnt = 0;
    __syncthreads();
    for (int p = c; p < HWn; p += 512)
        if (mask[b * HWn + p] > 0.5f) {
            int i = atomicAdd(&cnt, 1);
            plist[i] = p;
        }
    __syncthreads();
    float s = 0.f;
    for (int i = 0; i < cnt; i++) {
        int p = plist[i];
        s += x5n[(size_t)b * CMn + (size_t)c * HWn + p] * g_invnrm[b * HWn + p];
    }
    g_seeds[b * Cn + c] = s;
}

// corr[b,p] = mean_s relu(norm0[b,:,p] · seeds[s])
__global__ void corr_kernel(const float* __restrict__ x5n)
{
    __shared__ float ss[Bn * Cn];  // 32 KB
    const int b = blockIdx.x;
    const int p = blockIdx.y * 192 + threadIdx.x;
    for (int i = threadIdx.x; i < Bn * Cn; i += 192) ss[i] = g_seeds[i];
    __syncthreads();
    float acc[Bn] = {};
    const float invn = g_invnrm[b * HWn + p];
    const float* xp = x5n + (size_t)b * CMn + p;
    for (int c = 0; c < Cn; c++) {
        float x = xp[(size_t)c * HWn] * invn;
        #pragma unroll
        for (int s = 0; s < Bn; s++) acc[s] += x * ss[s * Cn + c];
    }
    float r = 0.f;
    #pragma unroll
    for (int s = 0; s < Bn; s++) r += fmaxf(acc[s], 0.f);
    g_corr[b * HWn + p] = r * (1.0f / Bn);
}

// per-image min-max normalization of corr
__global__ void cormap_kernel()
{
    __shared__ float smn[HWn], smx[HWn];
    const int b = blockIdx.x, p = threadIdx.x;
    const float v = g_corr[b * HWn + p];
    smn[p] = v; smx[p] = v;
    __syncthreads();
    for (int st = 512; st > 0; st >>= 1) {
        if (p < st && p + st < HWn) {
            smn[p] = fminf(smn[p], smn[p + st]);
            smx[p] = fmaxf(smx[p], smx[p + st]);
        }
        __syncthreads();
    }
    g_cormap[b * HWn + p] = (v - smn[0]) / (smx[0] - smn[0] + 1e-12f);
}

// proto[c] = mean over (b,p) of x5new * cormap
__global__ void proto_kernel(const float* __restrict__ x5n,
                             float* __restrict__ o_pro)
{
    __shared__ float sred[256];
    const int c = blockIdx.x, t = threadIdx.x;
    float s = 0.f;
    for (int n = t; n < NTOT; n += 256) {
        int b = n / HWn, p = n - b * HWn;
        s += x5n[(size_t)b * CMn + (size_t)c * HWn + p] * g_cormap[n];
    }
    sred[t] = s;
    __syncthreads();
    for (int st = 128; st > 0; st >>= 1) {
        if (t < st) sred[t] += sred[t + st];
        __syncthreads();
    }
    if (t == 0) {
        float v = sred[0] * (1.0f / NTOT);
        g_proto[c] = v;
        o_pro[c] = v;
    }
}

// out3 = x5new*(proto[c] + cormap[b,p])   (== x5*proto1 + x51)
__global__ void out3_kernel(const float* __restrict__ x5n,
                            float* __restrict__ o3)
{
    const int i = blockIdx.x * 256 + threadIdx.x;  // < B*C*HW
    const int b = i / CMn;
    const int r = i - b * CMn;
    const int c = r / HWn;
    const int p = r - c * HWn;
    o3[i] = x5n[i] * (g_proto[c] + g_cormap[b * HWn + p]);
}

// ---------------------------------------------------------------
extern "C" void kernel_launch(void* const* d_in, const int* in_sizes, int n_in,
                              void* d_out, int out_size)
{
    const float* x5    = (const float*)d_in[0];
    const float* convw = (const float*)d_in[1];
    const float* convb = (const float*)d_in[2];
    const float* qw    = (const float*)d_in[3];
    const float* qb    = (const float*)d_in[4];
    const float* kw    = (const float*)d_in[5];
    const float* kb    = (const float*)d_in[6];

    float* out    = (float*)d_out;
    float* o_x5   = out;                          // (B,C,H,W)
    float* o_pro  = out + (size_t)Bn * CMn;       // (C,)
    float* o_3    = o_pro + Cn;                   // (B,C,H,W)
    float* o_mask = o_3 + (size_t)Bn * CMn;       // (B,H,W)

    dim3 blk(256);
    dim3 gg(HWn / 64, Cn / 64, Bn);               // (9, 8, 16)

    conv_gemm<true,  0><<<gg, blk>>>(convw, x5,   convb, o_x5);    // x5new (output 0)
    conv_gemm<false, 1><<<gg, blk>>>(qw,    o_x5, qb,    nullptr); // -> g_q
    conv_gemm<false, 2><<<gg, blk>>>(kw,    o_x5, kb,    nullptr); // -> g_k

    scores_kernel<<<dim3(HWn / 64, Bn, Bn), blk>>>();              // 87 GF GEMM+max

    xw_mask_kernel<<<Bn, HWn>>>(o_mask);
    invnrm_kernel<<<NTOT / 256, 256>>>(o_x5);
    seeds_kernel<<<Bn, Cn>>>(o_x5, o_mask);
    corr_kernel<<<dim3(Bn, HWn / 192), 192>>>(o_x5);
    cormap_kernel<<<Bn, HWn>>>();
    proto_kernel<<<Cn, 256>>>(o_x5, o_pro);
    out3_kernel<<<(Bn * CMn) / 256, 256>>>(o_x5, o_3);
}

// round 2
// speedup vs baseline: 1.2573x; 1.2573x over previous
#include <cuda_runtime.h>
#include <math.h>
#include <stdint.h>

#define Bn   16
#define Cn   512
#define HWn  576
#define CMn  (Cn*HWn)     // 294912
#define NTOT (Bn*HWn)     // 9216

// ---------------- device scratch (no allocs allowed) ----------------
__device__ float g_q[Bn*CMn];        // q projection, (B, C, HW) layout
__device__ float g_k[Bn*CMn];        // k projection, (B, C, HW) layout
__device__ float g_colmax[NTOT*Bn];  // per-(n, bk) max over m
__device__ float g_invnrm[NTOT];     // 1/max(||x5[:,p]||, 1e-12)
__device__ float g_seeds[Bn*Cn];
__device__ float g_corr[NTOT];
__device__ float g_cormap[NTOT];
__device__ float g_proto[Cn];

// ---------------------------------------------------------------
// GEMM: Y[b,o,m] = sum_c W[o,c]*X[b,c,m] + bias[o] (+ X[b,o,m] if RES)
// ---------------------------------------------------------------
template<bool RES, int DST>
__global__ void __launch_bounds__(256) conv_gemm(const float* __restrict__ Wm,
                                                 const float* __restrict__ X,
                                                 const float* __restrict__ bias,
                                                 float* __restrict__ Yp)
{
    __shared__ __align__(16) float Ws[16][68];   // [c][o]
    __shared__ __align__(16) float Xs[16][68];   // [c][m]
    const int m0 = blockIdx.x * 64;
    const int o0 = blockIdx.y * 64;
    const int b  = blockIdx.z;
    const float* Xb = X + (size_t)b * CMn;
    const int t  = threadIdx.x;
    const int tx = t & 15, ty = t >> 4;

    float acc[4][4] = {};

    for (int c0 = 0; c0 < Cn; c0 += 16) {
        {
            const int ow = t >> 2;
            const int cv = (t & 3) * 4;
            float4 w4 = *(const float4*)(Wm + (size_t)(o0 + ow) * Cn + c0 + cv);
            Ws[cv + 0][ow] = w4.x;
            Ws[cv + 1][ow] = w4.y;
            Ws[cv + 2][ow] = w4.z;
            Ws[cv + 3][ow] = w4.w;
        }
        {
            const int cx = t >> 4;
            const int mv = (t & 15) * 4;
            *(float4*)&Xs[cx][mv] =
                *(const float4*)(Xb + (size_t)(c0 + cx) * HWn + m0 + mv);
        }
        __syncthreads();
        #pragma unroll
        for (int kk = 0; kk < 16; kk++) {
            float4 a4 = *(const float4*)&Ws[kk][ty * 4];
            float4 x4 = *(const float4*)&Xs[kk][tx * 4];
            float av[4] = {a4.x, a4.y, a4.z, a4.w};
            float xv[4] = {x4.x, x4.y, x4.z, x4.w};
            #pragma unroll
            for (int i = 0; i < 4; i++)
                #pragma unroll
                for (int j = 0; j < 4; j++)
                    acc[i][j] += av[i] * xv[j];
        }
        __syncthreads();
    }

    float* Y = (DST == 1) ? g_q : (DST == 2) ? g_k : Yp;
    #pragma unroll
    for (int i = 0; i < 4; i++) {
        const int o = o0 + ty * 4 + i;
        const int m = m0 + tx * 4;
        const float bb = bias[o];
        float4 r;
        r.x = acc[i][0] + bb;
        r.y = acc[i][1] + bb;
        r.z = acc[i][2] + bb;
        r.w = acc[i][3] + bb;
        if (RES) {
            float4 xr = *(const float4*)(X + (size_t)b * CMn + (size_t)o * HWn + m);
            r.x += xr.x; r.y += xr.y; r.z += xr.z; r.w += xr.w;
        }
        *(float4*)(Y + (size_t)b * CMn + (size_t)o * HWn + m) = r;
    }
}

// ---------------------------------------------------------------
// tf32 tensor-core scores kernel.
// For each n = bq*HW + mq, each bk: max over m of q[n]·k[bk,:,m].
// Values feed only an argmax -> tf32 precision is ample (margin ~1000x).
// Block tile 64(mq) x 64(mk), K-chunk 32, 8 warps: warp (w&3) -> m-strip of 16,
// (w>>2) -> n-half of 32. Each warp: m16n8k8 mma, 4 n-tiles.
// ---------------------------------------------------------------
__device__ __forceinline__ uint32_t f2tf32(float x) {
    uint32_t u;
    asm("cvt.rna.tf32.f32 %0, %1;" : "=r"(u) : "f"(x));
    return u;
}

__global__ void __launch_bounds__(256) scores_tc()
{
    __shared__ __align__(16) float Qs[32][68];
    __shared__ __align__(16) float Ks[32][68];
    __shared__ float red[64][9];

    const int mq0 = blockIdx.x * 64;
    const int bq  = blockIdx.y;
    const int bk  = blockIdx.z;
    const float* Qb = g_q + (size_t)bq * CMn;
    const float* Kb = g_k + (size_t)bk * CMn;

    const int t    = threadIdx.x;
    const int warp = t >> 5;
    const int lane = t & 31;
    const int wm   = (warp & 3) * 16;   // m offset of this warp's strip
    const int wn   = (warp >> 2) * 32;  // n offset of this warp's half
    const int lr   = lane >> 2;         // 0..7
    const int lc   = lane & 3;          // 0..3

    // global-load indexing for the cooperative tile fill
    const int gr = t >> 3;         // 0..31 (channel row within chunk)
    const int gc = (t & 7) * 8;    // 0..56 (col, 8 floats per thread)

    float rm0 = -1e30f, rm1 = -1e30f;   // running rowmax, rows wm+lr / wm+8+lr

    for (int mk0 = 0; mk0 < HWn; mk0 += 64) {
        float d[4][4] = {};   // 4 n-tiles x 4 accumulators

        for (int c0 = 0; c0 < Cn; c0 += 32) {
            // cooperative load + tf32 round into smem
            {
                const float* qp = Qb + (size_t)(c0 + gr) * HWn + mq0 + gc;
                const float* kp = Kb + (size_t)(c0 + gr) * HWn + mk0 + gc;
                float4 q1 = *(const float4*)(qp);
                float4 q2 = *(const float4*)(qp + 4);
                float4 k1 = *(const float4*)(kp);
                float4 k2 = *(const float4*)(kp + 4);
                float* qs = &Qs[gr][gc];
                float* ks = &Ks[gr][gc];
                qs[0] = __uint_as_float(f2tf32(q1.x));
                qs[1] = __uint_as_float(f2tf32(q1.y));
                qs[2] = __uint_as_float(f2tf32(q1.z));
                qs[3] = __uint_as_float(f2tf32(q1.w));
                qs[4] = __uint_as_float(f2tf32(q2.x));
                qs[5] = __uint_as_float(f2tf32(q2.y));
                qs[6] = __uint_as_float(f2tf32(q2.z));
                qs[7] = __uint_as_float(f2tf32(q2.w));
                ks[0] = __uint_as_float(f2tf32(k1.x));
                ks[1] = __uint_as_float(f2tf32(k1.y));
                ks[2] = __uint_as_float(f2tf32(k1.z));
                ks[3] = __uint_as_float(f2tf32(k1.w));
                ks[4] = __uint_as_float(f2tf32(k2.x));
                ks[5] = __uint_as_float(f2tf32(k2.y));
                ks[6] = __uint_as_float(f2tf32(k2.z));
                ks[7] = __uint_as_float(f2tf32(k2.w));
            }
            __syncthreads();

            #pragma unroll
            for (int ks8 = 0; ks8 < 4; ks8++) {
                const int k0 = ks8 * 8;
                uint32_t a0 = __float_as_uint(Qs[k0 + lc    ][wm + lr    ]);
                uint32_t a1 = __float_as_uint(Qs[k0 + lc    ][wm + 8 + lr]);
                uint32_t a2 = __float_as_uint(Qs[k0 + 4 + lc][wm + lr    ]);
                uint32_t a3 = __float_as_uint(Qs[k0 + 4 + lc][wm + 8 + lr]);
                #pragma unroll
                for (int j = 0; j < 4; j++) {
                    uint32_t b0 = __float_as_uint(Ks[k0 + lc    ][wn + j * 8 + lr]);
                    uint32_t b1 = __float_as_uint(Ks[k0 + 4 + lc][wn + j * 8 + lr]);
                    asm volatile(
                        "mma.sync.aligned.m16n8k8.row.col.f32.tf32.tf32.f32 "
                        "{%0,%1,%2,%3}, {%4,%5,%6,%7}, {%8,%9}, {%0,%1,%2,%3};"
                        : "+f"(d[j][0]), "+f"(d[j][1]), "+f"(d[j][2]), "+f"(d[j][3])
                        : "r"(a0), "r"(a1), "r"(a2), "r"(a3), "r"(b0), "r"(b1));
                }
            }
            __syncthreads();
        }

        // fold this mk-tile's 8 column values into the running row maxes
        #pragma unroll
        for (int j = 0; j < 4; j++) {
            rm0 = fmaxf(rm0, fmaxf(d[j][0], d[j][1]));
            rm1 = fmaxf(rm1, fmaxf(d[j][2], d[j][3]));
        }
    }

    // reduce across the 4 lanes of each quad (they hold disjoint columns)
    rm0 = fmaxf(rm0, __shfl_xor_sync(0xFFFFFFFFu, rm0, 1));
    rm0 = fmaxf(rm0, __shfl_xor_sync(0xFFFFFFFFu, rm0, 2));
    rm1 = fmaxf(rm1, __shfl_xor_sync(0xFFFFFFFFu, rm1, 1));
    rm1 = fmaxf(rm1, __shfl_xor_sync(0xFFFFFFFFu, rm1, 2));

    if (lc == 0) {
        red[wm + lr    ][warp] = rm0;
        red[wm + 8 + lr][warp] = rm1;
    }
    __syncthreads();

    if (t < 64) {
        const int ws = t >> 4;  // m-strip index -> warps ws and ws+4 hold it
        float m = fmaxf(red[t][ws], red[t][ws + 4]);
        g_colmax[(size_t)(bq * HWn + mq0 + t) * Bn + bk] = m;
    }
}

// ---------------------------------------------------------------
__global__ void xw_mask_kernel(float* __restrict__ o_mask)
{
    __shared__ float smax[HWn];
    const int b = blockIdx.x, p = threadIdx.x;
    const float* cm = g_colmax + (size_t)(b * HWn + p) * Bn;
    float s = 0.f;
    #pragma unroll
    for (int j = 0; j < Bn; j++) s += cm[j];
    smax[p] = s;
    __syncthreads();
    for (int st = 512; st > 0; st >>= 1) {
        if (p < st && p + st < HWn) smax[p] = fmaxf(smax[p], smax[p + st]);
        __syncthreads();
    }
    o_mask[b * HWn + p] = (s == smax[0]) ? 1.0f : 0.0f;
}

__global__ void invnrm_kernel(const float* __restrict__ x5n)
{
    const int n = blockIdx.x * blockDim.x + threadIdx.x;
    const int b = n / HWn, p = n - b * HWn;
    const float* xp = x5n + (size_t)b * CMn + p;
    float s = 0.f;
    for (int c = 0; c < Cn; c++) {
        float v = xp[(size_t)c * HWn];
        s += v * v;
    }
    g_invnrm[n] = 1.0f / fmaxf(sqrtf(s), 1e-12f);
}

__global__ void seeds_kernel(const float* __restrict__ x5n,
                             const float* __restrict__ mask)
{
    __shared__ int cnt;
    __shared__ int plist[HWn];
    const int b = blockIdx.x, c = threadIdx.x;
    if (c == 0) cnt = 0;
    __syncthreads();
    for (int p = c; p < HWn; p += 512)
        if (mask[b * HWn + p] > 0.5f) {
            int i = atomicAdd(&cnt, 1);
            plist[i] = p;
        }
    __syncthreads();
    float s = 0.f;
    for (int i = 0; i < cnt; i++) {
        int p = plist[i];
        s += x5n[(size_t)b * CMn + (size_t)c * HWn + p] * g_invnrm[b * HWn + p];
    }
    g_seeds[b * Cn + c] = s;
}

__global__ void corr_kernel(const float* __restrict__ x5n)
{
    __shared__ float ss[Bn * Cn];
    const int b = blockIdx.x;
    const int p = blockIdx.y * 192 + threadIdx.x;
    for (int i = threadIdx.x; i < Bn * Cn; i += 192) ss[i] = g_seeds[i];
    __syncthreads();
    float acc[Bn] = {};
    const float invn = g_invnrm[b * HWn + p];
    const float* xp = x5n + (size_t)b * CMn + p;
    for (int c = 0; c < Cn; c++) {
        float x = xp[(size_t)c * HWn] * invn;
        #pragma unroll
        for (int s = 0; s < Bn; s++) acc[s] += x * ss[s * Cn + c];
    }
    float r = 0.f;
    #pragma unroll
    for (int s = 0; s < Bn; s++) r += fmaxf(acc[s], 0.f);
    g_corr[b * HWn + p] = r * (1.0f / Bn);
}

__global__ void cormap_kernel()
{
    __shared__ float smn[HWn], smx[HWn];
    const int b = blockIdx.x, p = threadIdx.x;
    const float v = g_corr[b * HWn + p];
    smn[p] = v; smx[p] = v;
    __syncthreads();
    for (int st = 512; st > 0; st >>= 1) {
        if (p < st && p + st < HWn) {
            smn[p] = fminf(smn[p], smn[p + st]);
            smx[p] = fmaxf(smx[p], smx[p + st]);
        }
        __syncthreads();
    }
    g_cormap[b * HWn + p] = (v - smn[0]) / (smx[0] - smn[0] + 1e-12f);
}

__global__ void proto_kernel(const float* __restrict__ x5n,
                             float* __restrict__ o_pro)
{
    __shared__ float sred[256];
    const int c = blockIdx.x, t = threadIdx.x;
    float s = 0.f;
    for (int n = t; n < NTOT; n += 256) {
        int b = n / HWn, p = n - b * HWn;
        s += x5n[(size_t)b * CMn + (size_t)c * HWn + p] * g_cormap[n];
    }
    sred[t] = s;
    __syncthreads();
    for (int st = 128; st > 0; st >>= 1) {
        if (t < st) sred[t] += sred[t + st];
        __syncthreads();
    }
    if (t == 0) {
        float v = sred[0] * (1.0f / NTOT);
        g_proto[c] = v;
        o_pro[c] = v;
    }
}

__global__ void out3_kernel(const float* __restrict__ x5n,
                            float* __restrict__ o3)
{
    const int i = blockIdx.x * 256 + threadIdx.x;
    const int b = i / CMn;
    const int r = i - b * CMn;
    const int c = r / HWn;
    const int p = r - c * HWn;
    o3[i] = x5n[i] * (g_proto[c] + g_cormap[b * HWn + p]);
}

// ---------------------------------------------------------------
extern "C" void kernel_launch(void* const* d_in, const int* in_sizes, int n_in,
                              void* d_out, int out_size)
{
    const float* x5    = (const float*)d_in[0];
    const float* convw = (const float*)d_in[1];
    const float* convb = (const float*)d_in[2];
    const float* qw    = (const float*)d_in[3];
    const float* qb    = (const float*)d_in[4];
    const float* kw    = (const float*)d_in[5];
    const float* kb    = (const float*)d_in[6];

    float* out    = (float*)d_out;
    float* o_x5   = out;
    float* o_pro  = out + (size_t)Bn * CMn;
    float* o_3    = o_pro + Cn;
    float* o_mask = o_3 + (size_t)Bn * CMn;

    dim3 blk(256);
    dim3 gg(HWn / 64, Cn / 64, Bn);

    conv_gemm<true,  0><<<gg, blk>>>(convw, x5,   convb, o_x5);
    conv_gemm<false, 1><<<gg, blk>>>(qw,    o_x5, qb,    nullptr);
    conv_gemm<false, 2><<<gg, blk>>>(kw,    o_x5, kb,    nullptr);

    scores_tc<<<dim3(HWn / 64, Bn, Bn), blk>>>();   // tf32 tensor cores

    xw_mask_kernel<<<Bn, HWn>>>(o_mask);
    invnrm_kernel<<<NTOT / 256, 256>>>(o_x5);
    seeds_kernel<<<Bn, Cn>>>(o_x5, o_mask);
    corr_kernel<<<dim3(Bn, HWn / 192), 192>>>(o_x5);
    cormap_kernel<<<Bn, HWn>>>();
    proto_kernel<<<Cn, 256>>>(o_x5, o_pro);
    out3_kernel<<<(Bn * CMn) / 256, 256>>>(o_x5, o_3);
}

// round 3
// speedup vs baseline: 2.5719x; 2.0456x over previous
#include <cuda_runtime.h>
#include <math.h>
#include <stdint.h>

#define Bn   16
#define Cn   512
#define HWn  576
#define CMn  (Cn*HWn)     // 294912
#define NTOT (Bn*HWn)     // 9216
#define NH   144          // 64-col half-tiles per row (9216/64)

// ---------------- device scratch (no allocs allowed) ----------------
__device__ float g_q[Bn*CMn];        // q projection, (B, C, HW) layout
__device__ float g_k[Bn*CMn];        // k projection, (B, C, HW) layout
__device__ float g_part[NTOT*NH];    // per-row max over each 64-col half-tile
__device__ float g_invnrm[NTOT];
__device__ float g_seeds[Bn*Cn];
__device__ float g_corr[NTOT];
__device__ float g_cormap[NTOT];
__device__ float g_proto[Cn];

// ---------------------------------------------------------------
// GEMM: Y[b,o,m] = sum_c W[o,c]*X[b,c,m] + bias[o] (+ X[b,o,m] if RES)
// ---------------------------------------------------------------
template<bool RES, int DST>
__global__ void __launch_bounds__(256) conv_gemm(const float* __restrict__ Wm,
                                                 const float* __restrict__ X,
                                                 const float* __restrict__ bias,
                                                 float* __restrict__ Yp)
{
    __shared__ __align__(16) float Ws[16][68];
    __shared__ __align__(16) float Xs[16][68];
    const int m0 = blockIdx.x * 64;
    const int o0 = blockIdx.y * 64;
    const int b  = blockIdx.z;
    const float* Xb = X + (size_t)b * CMn;
    const int t  = threadIdx.x;
    const int tx = t & 15, ty = t >> 4;

    float acc[4][4] = {};

    for (int c0 = 0; c0 < Cn; c0 += 16) {
        {
            const int ow = t >> 2;
            const int cv = (t & 3) * 4;
            float4 w4 = *(const float4*)(Wm + (size_t)(o0 + ow) * Cn + c0 + cv);
            Ws[cv + 0][ow] = w4.x;
            Ws[cv + 1][ow] = w4.y;
            Ws[cv + 2][ow] = w4.z;
            Ws[cv + 3][ow] = w4.w;
        }
        {
            const int cx = t >> 4;
            const int mv = (t & 15) * 4;
            *(float4*)&Xs[cx][mv] =
                *(const float4*)(Xb + (size_t)(c0 + cx) * HWn + m0 + mv);
        }
        __syncthreads();
        #pragma unroll
        for (int kk = 0; kk < 16; kk++) {
            float4 a4 = *(const float4*)&Ws[kk][ty * 4];
            float4 x4 = *(const float4*)&Xs[kk][tx * 4];
            float av[4] = {a4.x, a4.y, a4.z, a4.w};
            float xv[4] = {x4.x, x4.y, x4.z, x4.w};
            #pragma unroll
            for (int i = 0; i < 4; i++)
                #pragma unroll
                for (int j = 0; j < 4; j++)
                    acc[i][j] += av[i] * xv[j];
        }
        __syncthreads();
    }

    float* Y = (DST == 1) ? g_q : (DST == 2) ? g_k : Yp;
    #pragma unroll
    for (int i = 0; i < 4; i++) {
        const int o = o0 + ty * 4 + i;
        const int m = m0 + tx * 4;
        const float bb = bias[o];
        float4 r;
        r.x = acc[i][0] + bb;
        r.y = acc[i][1] + bb;
        r.z = acc[i][2] + bb;
        r.w = acc[i][3] + bb;
        if (RES) {
            float4 xr = *(const float4*)(X + (size_t)b * CMn + (size_t)o * HWn + m);
            r.x += xr.x; r.y += xr.y; r.z += xr.z; r.w += xr.w;
        }
        *(float4*)(Y + (size_t)b * CMn + (size_t)o * HWn + m) = r;
    }
}

// ---------------------------------------------------------------
// tf32 scores GEMM, flattened 9216x9216x512, block tile 128x128,
// 8 warps (2m x 4n), warp tile 64x32, K-chunk 16 double-buffered
// via cp.async. Row-max per 64-col half-tile -> g_part.
// Operands fed as raw fp32 bits (HW tf32 truncation) - mask-safe.
// ---------------------------------------------------------------
#define KC   16          // k rows per chunk
#define LDT  136         // padded tile row stride (128 + 8): conflict-free frags
#define STAGEF (KC*LDT)  // floats per stage per tile

__device__ __forceinline__ void cp16(uint32_t dst, const float* src) {
    asm volatile("cp.async.cg.shared.global [%0], [%1], 16;\n"
                 :: "r"(dst), "l"(src));
}

__global__ void __launch_bounds__(256) scores_tc2()
{
    __shared__ __align__(16) float Qs[2][KC][LDT];
    __shared__ __align__(16) float Ks[2][KC][LDT];
    __shared__ float red[128][4];

    const int t    = threadIdx.x;
    const int warp = t >> 5;
    const int lane = t & 31;
    const int wm   = (warp & 1) * 64;
    const int wn   = (warp >> 1) * 32;
    const int lr   = lane >> 2;
    const int lc   = lane & 3;
    const int R0   = blockIdx.x * 128;   // q rows
    const int N0   = blockIdx.y * 128;   // k cols

    // per-thread cp.async source/dest (2 float4 per tile per chunk)
    const float* qsrc[2];
    const float* ksrc[2];
    uint32_t qdst[2], kdst[2];
    #pragma unroll
    for (int i = 0; i < 2; i++) {
        const int idx = t + i * 256;        // 0..511
        const int cl  = idx >> 5;           // 0..15
        const int m4  = (idx & 31) * 4;     // 0..124
        const int rq = R0 + m4;
        qsrc[i] = g_q + (size_t)(rq / HWn) * CMn + (size_t)cl * HWn + (rq % HWn);
        const int rk = N0 + m4;
        ksrc[i] = g_k + (size_t)(rk / HWn) * CMn + (size_t)cl * HWn + (rk % HWn);
        qdst[i] = (uint32_t)__cvta_generic_to_shared(&Qs[0][cl][m4]);
        kdst[i] = (uint32_t)__cvta_generic_to_shared(&Ks[0][cl][m4]);
    }
    const uint32_t stB = (uint32_t)(STAGEF * sizeof(float));

    float d[4][4][4];
    #pragma unroll
    for (int mi = 0; mi < 4; mi++)
        #pragma unroll
        for (int ni = 0; ni < 4; ni++)
            #pragma unroll
            for (int r = 0; r < 4; r++) d[mi][ni][r] = 0.f;

    // prologue: chunk 0 -> stage 0
    #pragma unroll
    for (int i = 0; i < 2; i++) {
        cp16(qdst[i], qsrc[i]);
        cp16(kdst[i], ksrc[i]);
    }
    asm volatile("cp.async.commit_group;\n" ::: "memory");

    const int NCH = Cn / KC;  // 32 chunks
    for (int cc = 0; cc < NCH; cc++) {
        if (cc + 1 < NCH) {
            const uint32_t so = ((cc + 1) & 1) * stB;
            const size_t go = (size_t)(cc + 1) * KC * HWn;
            #pragma unroll
            for (int i = 0; i < 2; i++) {
                cp16(qdst[i] + so, qsrc[i] + go);
                cp16(kdst[i] + so, ksrc[i] + go);
            }
        }
        asm volatile("cp.async.commit_group;\n" ::: "memory");
        asm volatile("cp.async.wait_group 1;\n" ::: "memory");
        __syncthreads();

        const int st = cc & 1;
        #pragma unroll
        for (int kf = 0; kf < 2; kf++) {
            const int k0 = kf * 8;
            uint32_t a[4][4];
            #pragma unroll
            for (int mi = 0; mi < 4; mi++) {
                a[mi][0] = __float_as_uint(Qs[st][k0 + lc    ][wm + mi * 16 + lr    ]);
                a[mi][1] = __float_as_uint(Qs[st][k0 + lc    ][wm + mi * 16 + 8 + lr]);
                a[mi][2] = __float_as_uint(Qs[st][k0 + lc + 4][wm + mi * 16 + lr    ]);
                a[mi][3] = __float_as_uint(Qs[st][k0 + lc + 4][wm + mi * 16 + 8 + lr]);
            }
            uint32_t b[4][2];
            #pragma unroll
            for (int ni = 0; ni < 4; ni++) {
                b[ni][0] = __float_as_uint(Ks[st][k0 + lc    ][wn + ni * 8 + lr]);
                b[ni][1] = __float_as_uint(Ks[st][k0 + lc + 4][wn + ni * 8 + lr]);
            }
            #pragma unroll
            for (int mi = 0; mi < 4; mi++)
                #pragma unroll
                for (int ni = 0; ni < 4; ni++)
                    asm volatile(
                        "mma.sync.aligned.m16n8k8.row.col.f32.tf32.tf32.f32 "
                        "{%0,%1,%2,%3}, {%4,%5,%6,%7}, {%8,%9}, {%0,%1,%2,%3};"
                        : "+f"(d[mi][ni][0]), "+f"(d[mi][ni][1]),
                          "+f"(d[mi][ni][2]), "+f"(d[mi][ni][3])
                        : "r"(a[mi][0]), "r"(a[mi][1]), "r"(a[mi][2]), "r"(a[mi][3]),
                          "r"(b[ni][0]), "r"(b[ni][1]));
        }
        __syncthreads();
    }

    // row maxes over this warp's 32 columns
    #pragma unroll
    for (int mi = 0; mi < 4; mi++) {
        float ra = -1e30f, rb = -1e30f;
        #pragma unroll
        for (int ni = 0; ni < 4; ni++) {
            ra = fmaxf(ra, fmaxf(d[mi][ni][0], d[mi][ni][1]));
            rb = fmaxf(rb, fmaxf(d[mi][ni][2], d[mi][ni][3]));
        }
        ra = fmaxf(ra, __shfl_xor_sync(0xFFFFFFFFu, ra, 1));
        ra = fmaxf(ra, __shfl_xor_sync(0xFFFFFFFFu, ra, 2));
        rb = fmaxf(rb, __shfl_xor_sync(0xFFFFFFFFu, rb, 1));
        rb = fmaxf(rb, __shfl_xor_sync(0xFFFFFFFFu, rb, 2));
        if (lc == 0) {
            red[wm + mi * 16 + lr    ][warp >> 1] = ra;
            red[wm + mi * 16 + 8 + lr][warp >> 1] = rb;
        }
    }
    __syncthreads();

    if (t < 128) {
        const float h0 = fmaxf(red[t][0], red[t][1]);   // cols [N0, N0+64)
        const float h1 = fmaxf(red[t][2], red[t][3]);   // cols [N0+64, N0+128)
        const size_t row = R0 + t;
        g_part[row * NH + blockIdx.y * 2    ] = h0;
        g_part[row * NH + blockIdx.y * 2 + 1] = h1;
    }
}

// ---------------------------------------------------------------
// x_w(n) = sum_bk max over the 9 half-tiles of bk; mask = (x_w == max).
// ---------------------------------------------------------------
__global__ void xw_mask_kernel(float* __restrict__ o_mask)
{
    __shared__ float smax[HWn];
    const int b = blockIdx.x, p = threadIdx.x;
    const float* gp = g_part + (size_t)(b * HWn + p) * NH;
    float s = 0.f;
    #pragma unroll
    for (int bk = 0; bk < Bn; bk++) {
        float m = gp[bk * 9];
        #pragma unroll
        for (int h = 1; h < 9; h++) m = fmaxf(m, gp[bk * 9 + h]);
        s += m;
    }
    smax[p] = s;
    __syncthreads();
    for (int st = 512; st > 0; st >>= 1) {
        if (p < st && p + st < HWn) smax[p] = fmaxf(smax[p], smax[p + st]);
        __syncthreads();
    }
    o_mask[b * HWn + p] = (s == smax[0]) ? 1.0f : 0.0f;
}

__global__ void invnrm_kernel(const float* __restrict__ x5n)
{
    const int n = blockIdx.x * blockDim.x + threadIdx.x;
    const int b = n / HWn, p = n - b * HWn;
    const float* xp = x5n + (size_t)b * CMn + p;
    float s = 0.f;
    for (int c = 0; c < Cn; c++) {
        float v = xp[(size_t)c * HWn];
        s += v * v;
    }
    g_invnrm[n] = 1.0f / fmaxf(sqrtf(s), 1e-12f);
}

__global__ void seeds_kernel(const float* __restrict__ x5n,
                             const float* __restrict__ mask)
{
    __shared__ int cnt;
    __shared__ int plist[HWn];
    const int b = blockIdx.x, c = threadIdx.x;
    if (c == 0) cnt = 0;
    __syncthreads();
    for (int p = c; p < HWn; p += 512)
        if (mask[b * HWn + p] > 0.5f) {
            int i = atomicAdd(&cnt, 1);
            plist[i] = p;
        }
    __syncthreads();
    float s = 0.f;
    for (int i = 0; i < cnt; i++) {
        int p = plist[i];
        s += x5n[(size_t)b * CMn + (size_t)c * HWn + p] * g_invnrm[b * HWn + p];
    }
    g_seeds[b * Cn + c] = s;
}

__global__ void corr_kernel(const float* __restrict__ x5n)
{
    __shared__ float ss[Bn * Cn];
    const int b = blockIdx.x;
    const int p = blockIdx.y * 192 + threadIdx.x;
    for (int i = threadIdx.x; i < Bn * Cn; i += 192) ss[i] = g_seeds[i];
    __syncthreads();
    float acc[Bn] = {};
    const float invn = g_invnrm[b * HWn + p];
    const float* xp = x5n + (size_t)b * CMn + p;
    for (int c = 0; c < Cn; c++) {
        float x = xp[(size_t)c * HWn] * invn;
        #pragma unroll
        for (int s = 0; s < Bn; s++) acc[s] += x * ss[s * Cn + c];
    }
    float r = 0.f;
    #pragma unroll
    for (int s = 0; s < Bn; s++) r += fmaxf(acc[s], 0.f);
    g_corr[b * HWn + p] = r * (1.0f / Bn);
}

__global__ void cormap_kernel()
{
    __shared__ float smn[HWn], smx[HWn];
    const int b = blockIdx.x, p = threadIdx.x;
    const float v = g_corr[b * HWn + p];
    smn[p] = v; smx[p] = v;
    __syncthreads();
    for (int st = 512; st > 0; st >>= 1) {
        if (p < st && p + st < HWn) {
            smn[p] = fminf(smn[p], smn[p + st]);
            smx[p] = fmaxf(smx[p], smx[p + st]);
        }
        __syncthreads();
    }
    g_cormap[b * HWn + p] = (v - smn[0]) / (smx[0] - smn[0] + 1e-12f);
}

__global__ void proto_kernel(const float* __restrict__ x5n,
                             float* __restrict__ o_pro)
{
    __shared__ float sred[256];
    const int c = blockIdx.x, t = threadIdx.x;
    float s = 0.f;
    for (int n = t; n < NTOT; n += 256) {
        int b = n / HWn, p = n - b * HWn;
        s += x5n[(size_t)b * CMn + (size_t)c * HWn + p] * g_cormap[n];
    }
    sred[t] = s;
    __syncthreads();
    for (int st = 128; st > 0; st >>= 1) {
        if (t < st) sred[t] += sred[t + st];
        __syncthreads();
    }
    if (t == 0) {
        float v = sred[0] * (1.0f / NTOT);
        g_proto[c] = v;
        o_pro[c] = v;
    }
}

__global__ void out3_kernel(const float* __restrict__ x5n,
                            float* __restrict__ o3)
{
    const int i = blockIdx.x * 256 + threadIdx.x;
    const int b = i / CMn;
    const int r = i - b * CMn;
    const int c = r / HWn;
    const int p = r - c * HWn;
    o3[i] = x5n[i] * (g_proto[c] + g_cormap[b * HWn + p]);
}

// ---------------------------------------------------------------
extern "C" void kernel_launch(void* const* d_in, const int* in_sizes, int n_in,
                              void* d_out, int out_size)
{
    const float* x5    = (const float*)d_in[0];
    const float* convw = (const float*)d_in[1];
    const float* convb = (const float*)d_in[2];
    const float* qw    = (const float*)d_in[3];
    const float* qb    = (const float*)d_in[4];
    const float* kw    = (const float*)d_in[5];
    const float* kb    = (const float*)d_in[6];

    float* out    = (float*)d_out;
    float* o_x5   = out;
    float* o_pro  = out + (size_t)Bn * CMn;
    float* o_3    = o_pro + Cn;
    float* o_mask = o_3 + (size_t)Bn * CMn;

    dim3 blk(256);
    dim3 gg(HWn / 64, Cn / 64, Bn);

    conv_gemm<true,  0><<<gg, blk>>>(convw, x5,   convb, o_x5);
    conv_gemm<false, 1><<<gg, blk>>>(qw,    o_x5, qb,    nullptr);
    conv_gemm<false, 2><<<gg, blk>>>(kw,    o_x5, kb,    nullptr);

    scores_tc2<<<dim3(NTOT / 128, NTOT / 128), 256>>>();   // 72x72 blocks

    xw_mask_kernel<<<Bn, HWn>>>(o_mask);
    invnrm_kernel<<<NTOT / 256, 256>>>(o_x5);
    seeds_kernel<<<Bn, Cn>>>(o_x5, o_mask);
    corr_kernel<<<dim3(Bn, HWn / 192), 192>>>(o_x5);
    cormap_kernel<<<Bn, HWn>>>();
    proto_kernel<<<Cn, 256>>>(o_x5, o_pro);
    out3_kernel<<<(Bn * CMn) / 256, 256>>>(o_x5, o_3);
}

// round 4
// speedup vs baseline: 3.2863x; 1.2778x over previous
#include <cuda_runtime.h>
#include <math.h>
#include <stdint.h>

#define Bn   16
#define Cn   512
#define HWn  576
#define CMn  (Cn*HWn)     // 294912
#define NTOT (Bn*HWn)     // 9216
#define NH   144          // 64-col half-tiles per row (9216/64)

// ---------------- device scratch (no allocs allowed) ----------------
__device__ float g_q[Bn*CMn];        // q projection, (B, C, HW) layout
__device__ float g_k[Bn*CMn];        // k projection, (B, C, HW) layout
__device__ float g_part[NTOT*NH];    // per-row max over each 64-col half-tile
__device__ float g_invnrm[NTOT];
__device__ float g_seeds[Bn*Cn];
__device__ float g_corr[NTOT];
__device__ float g_cormap[NTOT];
__device__ float g_proto[Cn];

__device__ __forceinline__ void cp16(uint32_t dst, const float* src) {
    asm volatile("cp.async.cg.shared.global [%0], [%1], 16;\n"
                 :: "r"(dst), "l"(src));
}
__device__ __forceinline__ uint32_t tf32r(float x) {   // round-to-nearest tf32
    uint32_t u;
    asm("cvt.rna.tf32.f32 %0, %1;" : "=r"(u) : "f"(x));
    return u;
}

#define KC   16          // k rows per chunk
#define LDT  136         // padded X/K/Q tile row stride
#define LDW  20          // padded W tile row stride

// ---------------------------------------------------------------
// Tensor-core conv GEMM: D[o,n] = sum_c W[o,c]*X[c,n] + bias[o]
//   n = b*HWn + m flattened over (B,HW); X[c,n] = Xin[b*CMn + c*HWn + m].
// MODE 0: split-precision tf32 (3 MMA passes, fp32-grade) + residual,
//         output -> Yp (x5new).  MODE 1 -> g_q, MODE 2 -> g_k (1 pass).
// Block tile 128(o) x 128(n), 8 warps (2x4), warp tile 64x32,
// K-chunk 16 double-buffered via cp.async.
// ---------------------------------------------------------------
template<int MODE>
__global__ void __launch_bounds__(256) conv_tc(const float* __restrict__ Wm,
                                               const float* __restrict__ Xin,
                                               const float* __restrict__ bias,
                                               float* __restrict__ Yp)
{
    __shared__ __align__(16) float Ws[2][128][LDW];   // [o][k]
    __shared__ __align__(16) float Xs[2][KC][LDT];    // [k][n]

    const int t    = threadIdx.x;
    const int warp = t >> 5;
    const int lane = t & 31;
    const int wm   = (warp & 1) * 64;
    const int wn   = (warp >> 1) * 32;
    const int lr   = lane >> 2;
    const int lc   = lane & 3;
    const int N0   = blockIdx.x * 128;   // flattened cols
    const int O0   = blockIdx.y * 128;   // output channels

    // cp.async addressing: per thread 2 W vectors + 2 X vectors per chunk
    const float* wsrc[2];
    const float* xsrc[2];
    uint32_t wdst[2], xdst[2];
    #pragma unroll
    for (int i = 0; i < 2; i++) {
        const int idx = t + i * 256;         // 0..511
        const int ow = idx >> 2;             // 0..127
        const int cv = (idx & 3) * 4;        // 0,4,8,12
        wsrc[i] = Wm + (size_t)(O0 + ow) * Cn + cv;
        wdst[i] = (uint32_t)__cvta_generic_to_shared(&Ws[0][ow][cv]);
        const int cl = idx >> 5;             // 0..15
        const int n4 = (idx & 31) * 4;       // 0..124
        const int col = N0 + n4;
        xsrc[i] = Xin + (size_t)(col / HWn) * CMn + (size_t)cl * HWn + (col % HWn);
        xdst[i] = (uint32_t)__cvta_generic_to_shared(&Xs[0][cl][n4]);
    }
    const uint32_t wstB = (uint32_t)(128 * LDW * sizeof(float));
    const uint32_t xstB = (uint32_t)(KC * LDT * sizeof(float));

    float d[4][4][4];
    #pragma unroll
    for (int mi = 0; mi < 4; mi++)
        #pragma unroll
        for (int ni = 0; ni < 4; ni++)
            #pragma unroll
            for (int r = 0; r < 4; r++) d[mi][ni][r] = 0.f;

    #pragma unroll
    for (int i = 0; i < 2; i++) {
        cp16(wdst[i], wsrc[i]);
        cp16(xdst[i], xsrc[i]);
    }
    asm volatile("cp.async.commit_group;\n" ::: "memory");

    const int NCH = Cn / KC;  // 32
    for (int cc = 0; cc < NCH; cc++) {
        if (cc + 1 < NCH) {
            const int s1 = (cc + 1) & 1;
            const int kof = (cc + 1) * KC;
            #pragma unroll
            for (int i = 0; i < 2; i++) {
                cp16(wdst[i] + s1 * wstB, wsrc[i] + kof);
                cp16(xdst[i] + s1 * xstB, xsrc[i] + (size_t)kof * HWn);
            }
        }
        asm volatile("cp.async.commit_group;\n" ::: "memory");
        asm volatile("cp.async.wait_group 1;\n" ::: "memory");
        __syncthreads();

        const int st = cc & 1;
        #pragma unroll
        for (int kf = 0; kf < 2; kf++) {
            const int k0 = kf * 8;
            uint32_t ah[4][4], al[4][4];
            #pragma unroll
            for (int mi = 0; mi < 4; mi++) {
                float f0 = Ws[st][wm + mi * 16 + lr    ][k0 + lc    ];
                float f1 = Ws[st][wm + mi * 16 + 8 + lr][k0 + lc    ];
                float f2 = Ws[st][wm + mi * 16 + lr    ][k0 + lc + 4];
                float f3 = Ws[st][wm + mi * 16 + 8 + lr][k0 + lc + 4];
                ah[mi][0] = tf32r(f0); ah[mi][1] = tf32r(f1);
                ah[mi][2] = tf32r(f2); ah[mi][3] = tf32r(f3);
                if (MODE == 0) {
                    al[mi][0] = tf32r(f0 - __uint_as_float(ah[mi][0]));
                    al[mi][1] = tf32r(f1 - __uint_as_float(ah[mi][1]));
                    al[mi][2] = tf32r(f2 - __uint_as_float(ah[mi][2]));
                    al[mi][3] = tf32r(f3 - __uint_as_float(ah[mi][3]));
                }
            }
            #pragma unroll
            for (int ni = 0; ni < 4; ni++) {
                float g0 = Xs[st][k0 + lc    ][wn + ni * 8 + lr];
                float g1 = Xs[st][k0 + lc + 4][wn + ni * 8 + lr];
                uint32_t bh0 = tf32r(g0), bh1 = tf32r(g1);
                uint32_t bl0 = 0, bl1 = 0;
                if (MODE == 0) {
                    bl0 = tf32r(g0 - __uint_as_float(bh0));
                    bl1 = tf32r(g1 - __uint_as_float(bh1));
                }
                #pragma unroll
                for (int mi = 0; mi < 4; mi++) {
                    asm volatile(
                        "mma.sync.aligned.m16n8k8.row.col.f32.tf32.tf32.f32 "
                        "{%0,%1,%2,%3}, {%4,%5,%6,%7}, {%8,%9}, {%0,%1,%2,%3};"
                        : "+f"(d[mi][ni][0]), "+f"(d[mi][ni][1]),
                          "+f"(d[mi][ni][2]), "+f"(d[mi][ni][3])
                        : "r"(ah[mi][0]), "r"(ah[mi][1]), "r"(ah[mi][2]), "r"(ah[mi][3]),
                          "r"(bh0), "r"(bh1));
                    if (MODE == 0) {
                        asm volatile(
                            "mma.sync.aligned.m16n8k8.row.col.f32.tf32.tf32.f32 "
                            "{%0,%1,%2,%3}, {%4,%5,%6,%7}, {%8,%9}, {%0,%1,%2,%3};"
                            : "+f"(d[mi][ni][0]), "+f"(d[mi][ni][1]),
                              "+f"(d[mi][ni][2]), "+f"(d[mi][ni][3])
                            : "r"(ah[mi][0]), "r"(ah[mi][1]), "r"(ah[mi][2]), "r"(ah[mi][3]),
                              "r"(bl0), "r"(bl1));
                        asm volatile(
                            "mma.sync.aligned.m16n8k8.row.col.f32.tf32.tf32.f32 "
                            "{%0,%1,%2,%3}, {%4,%5,%6,%7}, {%8,%9}, {%0,%1,%2,%3};"
                            : "+f"(d[mi][ni][0]), "+f"(d[mi][ni][1]),
                              "+f"(d[mi][ni][2]), "+f"(d[mi][ni][3])
                            : "r"(al[mi][0]), "r"(al[mi][1]), "r"(al[mi][2]), "r"(al[mi][3]),
                              "r"(bh0), "r"(bh1));
                    }
                }
            }
        }
        __syncthreads();
    }

    // epilogue: bias (+ residual), scatter as float2 pairs
    float* Y = (MODE == 1) ? g_q : (MODE == 2) ? g_k : Yp;
    #pragma unroll
    for (int mi = 0; mi < 4; mi++) {
        const int row0 = O0 + wm + mi * 16 + lr;
        const float b0 = bias[row0];
        const float b1 = bias[row0 + 8];
        #pragma unroll
        for (int ni = 0; ni < 4; ni++) {
            const int col = N0 + wn + ni * 8 + 2 * lc;
            const int bb  = col / HWn;
            const int m   = col - bb * HWn;
            float2 v0, v1;
            v0.x = d[mi][ni][0] + b0; v0.y = d[mi][ni][1] + b0;
            v1.x = d[mi][ni][2] + b1; v1.y = d[mi][ni][3] + b1;
            float* y0 = Y + (size_t)bb * CMn + (size_t)row0 * HWn + m;
            float* y1 = y0 + 8 * HWn;
            if (MODE == 0) {
                const float* x0 = Xin + (size_t)bb * CMn + (size_t)row0 * HWn + m;
                float2 r0 = *(const float2*)x0;
                float2 r1 = *(const float2*)(x0 + 8 * HWn);
                v0.x += r0.x; v0.y += r0.y;
                v1.x += r1.x; v1.y += r1.y;
            }
            *(float2*)y0 = v0;
            *(float2*)y1 = v1;
        }
    }
}

// ---------------------------------------------------------------
// tf32 scores GEMM (unchanged from R3): 9216x9216x512, tile 128x128.
// ---------------------------------------------------------------
__global__ void __launch_bounds__(256) scores_tc2()
{
    __shared__ __align__(16) float Qs[2][KC][LDT];
    __shared__ __align__(16) float Ks[2][KC][LDT];
    __shared__ float red[128][4];

    const int t    = threadIdx.x;
    const int warp = t >> 5;
    const int lane = t & 31;
    const int wm   = (warp & 1) * 64;
    const int wn   = (warp >> 1) * 32;
    const int lr   = lane >> 2;
    const int lc   = lane & 3;
    const int R0   = blockIdx.x * 128;
    const int N0   = blockIdx.y * 128;

    const float* qsrc[2];
    const float* ksrc[2];
    uint32_t qdst[2], kdst[2];
    #pragma unroll
    for (int i = 0; i < 2; i++) {
        const int idx = t + i * 256;
        const int cl  = idx >> 5;
        const int m4  = (idx & 31) * 4;
        const int rq = R0 + m4;
        qsrc[i] = g_q + (size_t)(rq / HWn) * CMn + (size_t)cl * HWn + (rq % HWn);
        const int rk = N0 + m4;
        ksrc[i] = g_k + (size_t)(rk / HWn) * CMn + (size_t)cl * HWn + (rk % HWn);
        qdst[i] = (uint32_t)__cvta_generic_to_shared(&Qs[0][cl][m4]);
        kdst[i] = (uint32_t)__cvta_generic_to_shared(&Ks[0][cl][m4]);
    }
    const uint32_t stB = (uint32_t)(KC * LDT * sizeof(float));

    float d[4][4][4];
    #pragma unroll
    for (int mi = 0; mi < 4; mi++)
        #pragma unroll
        for (int ni = 0; ni < 4; ni++)
            #pragma unroll
            for (int r = 0; r < 4; r++) d[mi][ni][r] = 0.f;

    #pragma unroll
    for (int i = 0; i < 2; i++) {
        cp16(qdst[i], qsrc[i]);
        cp16(kdst[i], ksrc[i]);
    }
    asm volatile("cp.async.commit_group;\n" ::: "memory");

    const int NCH = Cn / KC;
    for (int cc = 0; cc < NCH; cc++) {
        if (cc + 1 < NCH) {
            const uint32_t so = ((cc + 1) & 1) * stB;
            const size_t go = (size_t)(cc + 1) * KC * HWn;
            #pragma unroll
            for (int i = 0; i < 2; i++) {
                cp16(qdst[i] + so, qsrc[i] + go);
                cp16(kdst[i] + so, ksrc[i] + go);
            }
        }
        asm volatile("cp.async.commit_group;\n" ::: "memory");
        asm volatile("cp.async.wait_group 1;\n" ::: "memory");
        __syncthreads();

        const int st = cc & 1;
        #pragma unroll
        for (int kf = 0; kf < 2; kf++) {
            const int k0 = kf * 8;
            uint32_t a[4][4];
            #pragma unroll
            for (int mi = 0; mi < 4; mi++) {
                a[mi][0] = __float_as_uint(Qs[st][k0 + lc    ][wm + mi * 16 + lr    ]);
                a[mi][1] = __float_as_uint(Qs[st][k0 + lc    ][wm + mi * 16 + 8 + lr]);
                a[mi][2] = __float_as_uint(Qs[st][k0 + lc + 4][wm + mi * 16 + lr    ]);
                a[mi][3] = __float_as_uint(Qs[st][k0 + lc + 4][wm + mi * 16 + 8 + lr]);
            }
            uint32_t b[4][2];
            #pragma unroll
            for (int ni = 0; ni < 4; ni++) {
                b[ni][0] = __float_as_uint(Ks[st][k0 + lc    ][wn + ni * 8 + lr]);
                b[ni][1] = __float_as_uint(Ks[st][k0 + lc + 4][wn + ni * 8 + lr]);
            }
            #pragma unroll
            for (int mi = 0; mi < 4; mi++)
                #pragma unroll
                for (int ni = 0; ni < 4; ni++)
                    asm volatile(
                        "mma.sync.aligned.m16n8k8.row.col.f32.tf32.tf32.f32 "
                        "{%0,%1,%2,%3}, {%4,%5,%6,%7}, {%8,%9}, {%0,%1,%2,%3};"
                        : "+f"(d[mi][ni][0]), "+f"(d[mi][ni][1]),
                          "+f"(d[mi][ni][2]), "+f"(d[mi][ni][3])
                        : "r"(a[mi][0]), "r"(a[mi][1]), "r"(a[mi][2]), "r"(a[mi][3]),
                          "r"(b[ni][0]), "r"(b[ni][1]));
        }
        __syncthreads();
    }

    #pragma unroll
    for (int mi = 0; mi < 4; mi++) {
        float ra = -1e30f, rb = -1e30f;
        #pragma unroll
        for (int ni = 0; ni < 4; ni++) {
            ra = fmaxf(ra, fmaxf(d[mi][ni][0], d[mi][ni][1]));
            rb = fmaxf(rb, fmaxf(d[mi][ni][2], d[mi][ni][3]));
        }
        ra = fmaxf(ra, __shfl_xor_sync(0xFFFFFFFFu, ra, 1));
        ra = fmaxf(ra, __shfl_xor_sync(0xFFFFFFFFu, ra, 2));
        rb = fmaxf(rb, __shfl_xor_sync(0xFFFFFFFFu, rb, 1));
        rb = fmaxf(rb, __shfl_xor_sync(0xFFFFFFFFu, rb, 2));
        if (lc == 0) {
            red[wm + mi * 16 + lr    ][warp >> 1] = ra;
            red[wm + mi * 16 + 8 + lr][warp >> 1] = rb;
        }
    }
    __syncthreads();

    if (t < 128) {
        const float h0 = fmaxf(red[t][0], red[t][1]);
        const float h1 = fmaxf(red[t][2], red[t][3]);
        const size_t row = R0 + t;
        g_part[row * NH + blockIdx.y * 2    ] = h0;
        g_part[row * NH + blockIdx.y * 2 + 1] = h1;
    }
}

// ---------------------------------------------------------------
__global__ void xw_mask_kernel(float* __restrict__ o_mask)
{
    __shared__ float smax[HWn];
    const int b = blockIdx.x, p = threadIdx.x;
    const float* gp = g_part + (size_t)(b * HWn + p) * NH;
    float s = 0.f;
    #pragma unroll
    for (int bk = 0; bk < Bn; bk++) {
        float m = gp[bk * 9];
        #pragma unroll
        for (int h = 1; h < 9; h++) m = fmaxf(m, gp[bk * 9 + h]);
        s += m;
    }
    smax[p] = s;
    __syncthreads();
    for (int st = 512; st > 0; st >>= 1) {
        if (p < st && p + st < HWn) smax[p] = fmaxf(smax[p], smax[p + st]);
        __syncthreads();
    }
    o_mask[b * HWn + p] = (s == smax[0]) ? 1.0f : 0.0f;
}

__global__ void invnrm_kernel(const float* __restrict__ x5n)
{
    const int n = blockIdx.x * blockDim.x + threadIdx.x;
    const int b = n / HWn, p = n - b * HWn;
    const float* xp = x5n + (size_t)b * CMn + p;
    float s = 0.f;
    for (int c = 0; c < Cn; c++) {
        float v = xp[(size_t)c * HWn];
        s += v * v;
    }
    g_invnrm[n] = 1.0f / fmaxf(sqrtf(s), 1e-12f);
}

__global__ void seeds_kernel(const float* __restrict__ x5n,
                             const float* __restrict__ mask)
{
    __shared__ int cnt;
    __shared__ int plist[HWn];
    const int b = blockIdx.x, c = threadIdx.x;
    if (c == 0) cnt = 0;
    __syncthreads();
    for (int p = c; p < HWn; p += 512)
        if (mask[b * HWn + p] > 0.5f) {
            int i = atomicAdd(&cnt, 1);
            plist[i] = p;
        }
    __syncthreads();
    float s = 0.f;
    for (int i = 0; i < cnt; i++) {
        int p = plist[i];
        s += x5n[(size_t)b * CMn + (size_t)c * HWn + p] * g_invnrm[b * HWn + p];
    }
    g_seeds[b * Cn + c] = s;
}

__global__ void corr_kernel(const float* __restrict__ x5n)
{
    __shared__ float ss[Bn * Cn];
    const int b = blockIdx.x;
    const int p = blockIdx.y * 192 + threadIdx.x;
    for (int i = threadIdx.x; i < Bn * Cn; i += 192) ss[i] = g_seeds[i];
    __syncthreads();
    float acc[Bn] = {};
    const float invn = g_invnrm[b * HWn + p];
    const float* xp = x5n + (size_t)b * CMn + p;
    for (int c = 0; c < Cn; c++) {
        float x = xp[(size_t)c * HWn] * invn;
        #pragma unroll
        for (int s = 0; s < Bn; s++) acc[s] += x * ss[s * Cn + c];
    }
    float r = 0.f;
    #pragma unroll
    for (int s = 0; s < Bn; s++) r += fmaxf(acc[s], 0.f);
    g_corr[b * HWn + p] = r * (1.0f / Bn);
}

__global__ void cormap_kernel()
{
    __shared__ float smn[HWn], smx[HWn];
    const int b = blockIdx.x, p = threadIdx.x;
    const float v = g_corr[b * HWn + p];
    smn[p] = v; smx[p] = v;
    __syncthreads();
    for (int st = 512; st > 0; st >>= 1) {
        if (p < st && p + st < HWn) {
            smn[p] = fminf(smn[p], smn[p + st]);
            smx[p] = fmaxf(smx[p], smx[p + st]);
        }
        __syncthreads();
    }
    g_cormap[b * HWn + p] = (v - smn[0]) / (smx[0] - smn[0] + 1e-12f);
}

__global__ void proto_kernel(const float* __restrict__ x5n,
                             float* __restrict__ o_pro)
{
    __shared__ float sred[256];
    const int c = blockIdx.x, t = threadIdx.x;
    float s = 0.f;
    for (int n = t; n < NTOT; n += 256) {
        int b = n / HWn, p = n - b * HWn;
        s += x5n[(size_t)b * CMn + (size_t)c * HWn + p] * g_cormap[n];
    }
    sred[t] = s;
    __syncthreads();
    for (int st = 128; st > 0; st >>= 1) {
        if (t < st) sred[t] += sred[t + st];
        __syncthreads();
    }
    if (t == 0) {
        float v = sred[0] * (1.0f / NTOT);
        g_proto[c] = v;
        o_pro[c] = v;
    }
}

__global__ void out3_kernel(const float* __restrict__ x5n,
                            float* __restrict__ o3)
{
    const int i = blockIdx.x * 256 + threadIdx.x;
    const int b = i / CMn;
    const int r = i - b * CMn;
    const int c = r / HWn;
    const int p = r - c * HWn;
    o3[i] = x5n[i] * (g_proto[c] + g_cormap[b * HWn + p]);
}

// ---------------------------------------------------------------
extern "C" void kernel_launch(void* const* d_in, const int* in_sizes, int n_in,
                              void* d_out, int out_size)
{
    const float* x5    = (const float*)d_in[0];
    const float* convw = (const float*)d_in[1];
    const float* convb = (const float*)d_in[2];
    const float* qw    = (const float*)d_in[3];
    const float* qb    = (const float*)d_in[4];
    const float* kw    = (const float*)d_in[5];
    const float* kb    = (const float*)d_in[6];

    float* out    = (float*)d_out;
    float* o_x5   = out;
    float* o_pro  = out + (size_t)Bn * CMn;
    float* o_3    = o_pro + Cn;
    float* o_mask = o_3 + (size_t)Bn * CMn;

    dim3 cgrid(NTOT / 128, Cn / 128);   // (72, 4)

    conv_tc<0><<<cgrid, 256>>>(convw, x5,   convb, o_x5);   // x5new (split tf32)
    conv_tc<1><<<cgrid, 256>>>(qw,    o_x5, qb,    nullptr);
    conv_tc<2><<<cgrid, 256>>>(kw,    o_x5, kb,    nullptr);

    scores_tc2<<<dim3(NTOT / 128, NTOT / 128), 256>>>();

    xw_mask_kernel<<<Bn, HWn>>>(o_mask);
    invnrm_kernel<<<NTOT / 256, 256>>>(o_x5);
    seeds_kernel<<<Bn, Cn>>>(o_x5, o_mask);
    corr_kernel<<<dim3(Bn, HWn / 192), 192>>>(o_x5);
    cormap_kernel<<<Bn, HWn>>>();
    proto_kernel<<<Cn, 256>>>(o_x5, o_pro);
    out3_kernel<<<(Bn * CMn) / 256, 256>>>(o_x5, o_3);
}

// round 5
// speedup vs baseline: 4.3169x; 1.3136x over previous
#include <cuda_runtime.h>
#include <cuda_bf16.h>
#include <math.h>
#include <stdint.h>

#define Bn   16
#define Cn   512
#define HWn  576
#define CMn  (Cn*HWn)     // 294912
#define NTOT (Bn*HWn)     // 9216
#define NH   144          // 64-col half-tiles per row (9216/64)

// ---------------- device scratch (no allocs allowed) ----------------
__device__ __nv_bfloat16 g_qh[(size_t)NTOT*Cn];  // q, [n][c] bf16 transposed
__device__ __nv_bfloat16 g_kh[(size_t)NTOT*Cn];  // k, [n][c] bf16 transposed
__device__ float g_part[NTOT*NH];    // per-row max over each 64-col half-tile
__device__ float g_invnrm[NTOT];
__device__ float g_seeds[Bn*Cn];
__device__ float g_corr[NTOT];
__device__ float g_cormap[NTOT];
__device__ float g_proto[Cn];

__device__ __forceinline__ void cp16(uint32_t dst, const void* src) {
    asm volatile("cp.async.cg.shared.global [%0], [%1], 16;\n"
                 :: "r"(dst), "l"(src));
}
__device__ __forceinline__ uint32_t tf32r(float x) {
    uint32_t u;
    asm("cvt.rna.tf32.f32 %0, %1;" : "=r"(u) : "f"(x));
    return u;
}

#define KC   16          // k rows per chunk
#define LDT  136         // padded fp32 X tile row stride
#define LDW  20          // padded fp32 W tile row stride

// ---------------------------------------------------------------
// Tensor-core conv GEMM: D[o,n] = sum_c W[o,c]*X[c,n] + bias[o]
// MODE 0: split tf32 (3 passes) + residual -> Yp fp32 (x5new).
// MODE 1/2: single tf32 pass -> g_qh / g_kh, bf16, TRANSPOSED [n][c].
// ---------------------------------------------------------------
template<int MODE>
__global__ void __launch_bounds__(256) conv_tc(const float* __restrict__ Wm,
                                               const float* __restrict__ Xin,
                                               const float* __restrict__ bias,
                                               float* __restrict__ Yp)
{
    __shared__ __align__(16) float Ws[2][128][LDW];   // [o][k]
    __shared__ __align__(16) float Xs[2][KC][LDT];    // [k][n]

    const int t    = threadIdx.x;
    const int warp = t >> 5;
    const int lane = t & 31;
    const int wm   = (warp & 1) * 64;
    const int wn   = (warp >> 1) * 32;
    const int lr   = lane >> 2;
    const int lc   = lane & 3;
    const int N0   = blockIdx.x * 128;
    const int O0   = blockIdx.y * 128;

    const float* wsrc[2];
    const float* xsrc[2];
    uint32_t wdst[2], xdst[2];
    #pragma unroll
    for (int i = 0; i < 2; i++) {
        const int idx = t + i * 256;
        const int ow = idx >> 2;
        const int cv = (idx & 3) * 4;
        wsrc[i] = Wm + (size_t)(O0 + ow) * Cn + cv;
        wdst[i] = (uint32_t)__cvta_generic_to_shared(&Ws[0][ow][cv]);
        const int cl = idx >> 5;
        const int n4 = (idx & 31) * 4;
        const int col = N0 + n4;
        xsrc[i] = Xin + (size_t)(col / HWn) * CMn + (size_t)cl * HWn + (col % HWn);
        xdst[i] = (uint32_t)__cvta_generic_to_shared(&Xs[0][cl][n4]);
    }
    const uint32_t wstB = (uint32_t)(128 * LDW * sizeof(float));
    const uint32_t xstB = (uint32_t)(KC * LDT * sizeof(float));

    float d[4][4][4];
    #pragma unroll
    for (int mi = 0; mi < 4; mi++)
        #pragma unroll
        for (int ni = 0; ni < 4; ni++)
            #pragma unroll
            for (int r = 0; r < 4; r++) d[mi][ni][r] = 0.f;

    #pragma unroll
    for (int i = 0; i < 2; i++) {
        cp16(wdst[i], wsrc[i]);
        cp16(xdst[i], xsrc[i]);
    }
    asm volatile("cp.async.commit_group;\n" ::: "memory");

    const int NCH = Cn / KC;
    for (int cc = 0; cc < NCH; cc++) {
        if (cc + 1 < NCH) {
            const int s1 = (cc + 1) & 1;
            const int kof = (cc + 1) * KC;
            #pragma unroll
            for (int i = 0; i < 2; i++) {
                cp16(wdst[i] + s1 * wstB, wsrc[i] + kof);
                cp16(xdst[i] + s1 * xstB, xsrc[i] + (size_t)kof * HWn);
            }
        }
        asm volatile("cp.async.commit_group;\n" ::: "memory");
        asm volatile("cp.async.wait_group 1;\n" ::: "memory");
        __syncthreads();

        const int st = cc & 1;
        #pragma unroll
        for (int kf = 0; kf < 2; kf++) {
            const int k0 = kf * 8;
            uint32_t ah[4][4], al[4][4];
            #pragma unroll
            for (int mi = 0; mi < 4; mi++) {
                float f0 = Ws[st][wm + mi * 16 + lr    ][k0 + lc    ];
                float f1 = Ws[st][wm + mi * 16 + 8 + lr][k0 + lc    ];
                float f2 = Ws[st][wm + mi * 16 + lr    ][k0 + lc + 4];
                float f3 = Ws[st][wm + mi * 16 + 8 + lr][k0 + lc + 4];
                ah[mi][0] = tf32r(f0); ah[mi][1] = tf32r(f1);
                ah[mi][2] = tf32r(f2); ah[mi][3] = tf32r(f3);
                if (MODE == 0) {
                    al[mi][0] = tf32r(f0 - __uint_as_float(ah[mi][0]));
                    al[mi][1] = tf32r(f1 - __uint_as_float(ah[mi][1]));
                    al[mi][2] = tf32r(f2 - __uint_as_float(ah[mi][2]));
                    al[mi][3] = tf32r(f3 - __uint_as_float(ah[mi][3]));
                }
            }
            #pragma unroll
            for (int ni = 0; ni < 4; ni++) {
                float g0 = Xs[st][k0 + lc    ][wn + ni * 8 + lr];
                float g1 = Xs[st][k0 + lc + 4][wn + ni * 8 + lr];
                uint32_t bh0 = tf32r(g0), bh1 = tf32r(g1);
                uint32_t bl0 = 0, bl1 = 0;
                if (MODE == 0) {
                    bl0 = tf32r(g0 - __uint_as_float(bh0));
                    bl1 = tf32r(g1 - __uint_as_float(bh1));
                }
                #pragma unroll
                for (int mi = 0; mi < 4; mi++) {
                    asm volatile(
                        "mma.sync.aligned.m16n8k8.row.col.f32.tf32.tf32.f32 "
                        "{%0,%1,%2,%3}, {%4,%5,%6,%7}, {%8,%9}, {%0,%1,%2,%3};"
                        : "+f"(d[mi][ni][0]), "+f"(d[mi][ni][1]),
                          "+f"(d[mi][ni][2]), "+f"(d[mi][ni][3])
                        : "r"(ah[mi][0]), "r"(ah[mi][1]), "r"(ah[mi][2]), "r"(ah[mi][3]),
                          "r"(bh0), "r"(bh1));
                    if (MODE == 0) {
                        asm volatile(
                            "mma.sync.aligned.m16n8k8.row.col.f32.tf32.tf32.f32 "
                            "{%0,%1,%2,%3}, {%4,%5,%6,%7}, {%8,%9}, {%0,%1,%2,%3};"
                            : "+f"(d[mi][ni][0]), "+f"(d[mi][ni][1]),
                              "+f"(d[mi][ni][2]), "+f"(d[mi][ni][3])
                            : "r"(ah[mi][0]), "r"(ah[mi][1]), "r"(ah[mi][2]), "r"(ah[mi][3]),
                              "r"(bl0), "r"(bl1));
                        asm volatile(
                            "mma.sync.aligned.m16n8k8.row.col.f32.tf32.tf32.f32 "
                            "{%0,%1,%2,%3}, {%4,%5,%6,%7}, {%8,%9}, {%0,%1,%2,%3};"
                            : "+f"(d[mi][ni][0]), "+f"(d[mi][ni][1]),
                              "+f"(d[mi][ni][2]), "+f"(d[mi][ni][3])
                            : "r"(al[mi][0]), "r"(al[mi][1]), "r"(al[mi][2]), "r"(al[mi][3]),
                              "r"(bh0), "r"(bh1));
                    }
                }
            }
        }
        __syncthreads();
    }

    // epilogue
    #pragma unroll
    for (int mi = 0; mi < 4; mi++) {
        const int row0 = O0 + wm + mi * 16 + lr;
        const float b0 = bias[row0];
        const float b1 = bias[row0 + 8];
        #pragma unroll
        for (int ni = 0; ni < 4; ni++) {
            const int col = N0 + wn + ni * 8 + 2 * lc;     // flattened n
            if (MODE == 0) {
                const int bb = col / HWn;
                const int m  = col - bb * HWn;
                float2 v0, v1;
                v0.x = d[mi][ni][0] + b0; v0.y = d[mi][ni][1] + b0;
                v1.x = d[mi][ni][2] + b1; v1.y = d[mi][ni][3] + b1;
                const float* x0 = Xin + (size_t)bb * CMn + (size_t)row0 * HWn + m;
                float2 r0 = *(const float2*)x0;
                float2 r1 = *(const float2*)(x0 + 8 * HWn);
                v0.x += r0.x; v0.y += r0.y;
                v1.x += r1.x; v1.y += r1.y;
                float* y0 = Yp + (size_t)bb * CMn + (size_t)row0 * HWn + m;
                *(float2*)y0 = v0;
                *(float2*)(y0 + 8 * HWn) = v1;
            } else {
                __nv_bfloat16* Yh = (MODE == 1) ? g_qh : g_kh;
                Yh[(size_t)col       * Cn + row0    ] = __float2bfloat16(d[mi][ni][0] + b0);
                Yh[(size_t)(col + 1) * Cn + row0    ] = __float2bfloat16(d[mi][ni][1] + b0);
                Yh[(size_t)col       * Cn + row0 + 8] = __float2bfloat16(d[mi][ni][2] + b1);
                Yh[(size_t)(col + 1) * Cn + row0 + 8] = __float2bfloat16(d[mi][ni][3] + b1);
            }
        }
    }
}

// ---------------------------------------------------------------
// bf16 scores GEMM: 9216x9216x512, tile 128x128, m16n8k16,
// smem [row][k] bf16 (pad 24), packed 32-bit fragment loads.
// Row-max per 64-col half-tile -> g_part.
// ---------------------------------------------------------------
#define LDQ 24    // bf16 elems per smem row (16 + 8 pad): conflict-free

__global__ void __launch_bounds__(256) scores_bf()
{
    __shared__ __align__(16) __nv_bfloat16 Qs[2][128][LDQ];
    __shared__ __align__(16) __nv_bfloat16 Ks[2][128][LDQ];
    __shared__ float red[128][4];

    const int t    = threadIdx.x;
    const int warp = t >> 5;
    const int lane = t & 31;
    const int wm   = (warp & 1) * 64;
    const int wn   = (warp >> 1) * 32;
    const int lr   = lane >> 2;
    const int lc   = lane & 3;
    const int R0   = blockIdx.x * 128;
    const int N0   = blockIdx.y * 128;

    const int row  = t >> 1;      // 0..127
    const int half = t & 1;       // 8-elem half of the 16-elem k-run
    const __nv_bfloat16* qsrc = g_qh + (size_t)(R0 + row) * Cn + half * 8;
    const __nv_bfloat16* ksrc = g_kh + (size_t)(N0 + row) * Cn + half * 8;
    const uint32_t qdst = (uint32_t)__cvta_generic_to_shared(&Qs[0][row][half * 8]);
    const uint32_t kdst = (uint32_t)__cvta_generic_to_shared(&Ks[0][row][half * 8]);
    const uint32_t stB  = (uint32_t)(128 * LDQ * sizeof(__nv_bfloat16));  // 6144

    float d[4][4][4];
    #pragma unroll
    for (int mi = 0; mi < 4; mi++)
        #pragma unroll
        for (int ni = 0; ni < 4; ni++)
            #pragma unroll
            for (int r = 0; r < 4; r++) d[mi][ni][r] = 0.f;

    cp16(qdst, qsrc);
    cp16(kdst, ksrc);
    asm volatile("cp.async.commit_group;\n" ::: "memory");

    const int NCH = Cn / KC;   // 32
    for (int cc = 0; cc < NCH; cc++) {
        if (cc + 1 < NCH) {
            const uint32_t so = ((cc + 1) & 1) * stB;
            const int go = (cc + 1) * KC;
            cp16(qdst + so, qsrc + go);
            cp16(kdst + so, ksrc + go);
        }
        asm volatile("cp.async.commit_group;\n" ::: "memory");
        asm volatile("cp.async.wait_group 1;\n" ::: "memory");
        __syncthreads();

        const int st = cc & 1;
        uint32_t a[4][4];
        #pragma unroll
        for (int mi = 0; mi < 4; mi++) {
            a[mi][0] = *(const uint32_t*)&Qs[st][wm + mi * 16 + lr    ][2 * lc    ];
            a[mi][1] = *(const uint32_t*)&Qs[st][wm + mi * 16 + 8 + lr][2 * lc    ];
            a[mi][2] = *(const uint32_t*)&Qs[st][wm + mi * 16 + lr    ][2 * lc + 8];
            a[mi][3] = *(const uint32_t*)&Qs[st][wm + mi * 16 + 8 + lr][2 * lc + 8];
        }
        uint32_t b[4][2];
        #pragma unroll
        for (int ni = 0; ni < 4; ni++) {
            b[ni][0] = *(const uint32_t*)&Ks[st][wn + ni * 8 + lr][2 * lc    ];
            b[ni][1] = *(const uint32_t*)&Ks[st][wn + ni * 8 + lr][2 * lc + 8];
        }
        #pragma unroll
        for (int mi = 0; mi < 4; mi++)
            #pragma unroll
            for (int ni = 0; ni < 4; ni++)
                asm volatile(
                    "mma.sync.aligned.m16n8k16.row.col.f32.bf16.bf16.f32 "
                    "{%0,%1,%2,%3}, {%4,%5,%6,%7}, {%8,%9}, {%0,%1,%2,%3};"
                    : "+f"(d[mi][ni][0]), "+f"(d[mi][ni][1]),
                      "+f"(d[mi][ni][2]), "+f"(d[mi][ni][3])
                    : "r"(a[mi][0]), "r"(a[mi][1]), "r"(a[mi][2]), "r"(a[mi][3]),
                      "r"(b[ni][0]), "r"(b[ni][1]));
        __syncthreads();
    }

    #pragma unroll
    for (int mi = 0; mi < 4; mi++) {
        float ra = -1e30f, rb = -1e30f;
        #pragma unroll
        for (int ni = 0; ni < 4; ni++) {
            ra = fmaxf(ra, fmaxf(d[mi][ni][0], d[mi][ni][1]));
            rb = fmaxf(rb, fmaxf(d[mi][ni][2], d[mi][ni][3]));
        }
        ra = fmaxf(ra, __shfl_xor_sync(0xFFFFFFFFu, ra, 1));
        ra = fmaxf(ra, __shfl_xor_sync(0xFFFFFFFFu, ra, 2));
        rb = fmaxf(rb, __shfl_xor_sync(0xFFFFFFFFu, rb, 1));
        rb = fmaxf(rb, __shfl_xor_sync(0xFFFFFFFFu, rb, 2));
        if (lc == 0) {
            red[wm + mi * 16 + lr    ][warp >> 1] = ra;
            red[wm + mi * 16 + 8 + lr][warp >> 1] = rb;
        }
    }
    __syncthreads();

    if (t < 128) {
        const float h0 = fmaxf(red[t][0], red[t][1]);
        const float h1 = fmaxf(red[t][2], red[t][3]);
        const size_t r2 = R0 + t;
        g_part[r2 * NH + blockIdx.y * 2    ] = h0;
        g_part[r2 * NH + blockIdx.y * 2 + 1] = h1;
    }
}

// ---------------------------------------------------------------
__global__ void xw_mask_kernel(float* __restrict__ o_mask)
{
    __shared__ float smax[HWn];
    const int b = blockIdx.x, p = threadIdx.x;
    const float* gp = g_part + (size_t)(b * HWn + p) * NH;
    float s = 0.f;
    #pragma unroll
    for (int bk = 0; bk < Bn; bk++) {
        float m = gp[bk * 9];
        #pragma unroll
        for (int h = 1; h < 9; h++) m = fmaxf(m, gp[bk * 9 + h]);
        s += m;
    }
    smax[p] = s;
    __syncthreads();
    for (int st = 512; st > 0; st >>= 1) {
        if (p < st && p + st < HWn) smax[p] = fmaxf(smax[p], smax[p + st]);
        __syncthreads();
    }
    o_mask[b * HWn + p] = (s == smax[0]) ? 1.0f : 0.0f;
}

// invnrm: grid 144, block (64,4); coalesced, wide parallelism
__global__ void invnrm_kernel(const float* __restrict__ x5n)
{
    __shared__ float part[4][64];
    const int b  = blockIdx.x / 9;
    const int p0 = (blockIdx.x % 9) * 64;
    const int px = threadIdx.x;
    const int cy = threadIdx.y;
    const float* xp = x5n + (size_t)b * CMn + p0 + px;
    float s = 0.f;
    for (int c = cy; c < Cn; c += 4) {
        float v = xp[(size_t)c * HWn];
        s += v * v;
    }
    part[cy][px] = s;
    __syncthreads();
    if (cy == 0) {
        float tot = part[0][px] + part[1][px] + part[2][px] + part[3][px];
        g_invnrm[b * HWn + p0 + px] = 1.0f / fmaxf(sqrtf(tot), 1e-12f);
    }
}

__global__ void seeds_kernel(const float* __restrict__ x5n,
                             const float* __restrict__ mask)
{
    __shared__ int cnt;
    __shared__ int plist[HWn];
    const int b = blockIdx.x, c = threadIdx.x;
    if (c == 0) cnt = 0;
    __syncthreads();
    for (int p = c; p < HWn; p += 512)
        if (mask[b * HWn + p] > 0.5f) {
            int i = atomicAdd(&cnt, 1);
            plist[i] = p;
        }
    __syncthreads();
    float s = 0.f;
    for (int i = 0; i < cnt; i++) {
        int p = plist[i];
        s += x5n[(size_t)b * CMn + (size_t)c * HWn + p] * g_invnrm[b * HWn + p];
    }
    g_seeds[b * Cn + c] = s;
}

// corr: seeds transposed in smem -> float4 broadcast loads
__global__ void corr_kernel(const float* __restrict__ x5n)
{
    __shared__ __align__(16) float ssT[Cn][Bn];   // 32 KB
    const int b = blockIdx.x;
    const int p = blockIdx.y * 64 + threadIdx.x;
    for (int i = threadIdx.x; i < Cn * Bn; i += 64) {
        int c = i >> 4, s = i & 15;
        ssT[c][s] = g_seeds[s * Cn + c];
    }
    __syncthreads();
    float acc[Bn] = {};
    const float invn = g_invnrm[b * HWn + p];
    const float* xp = x5n + (size_t)b * CMn + p;
    for (int c = 0; c < Cn; c++) {
        float x = xp[(size_t)c * HWn];
        #pragma unroll
        for (int s4 = 0; s4 < 4; s4++) {
            float4 sv = *(const float4*)&ssT[c][s4 * 4];
            acc[s4 * 4 + 0] += x * sv.x;
            acc[s4 * 4 + 1] += x * sv.y;
            acc[s4 * 4 + 2] += x * sv.z;
            acc[s4 * 4 + 3] += x * sv.w;
        }
    }
    float r = 0.f;
    #pragma unroll
    for (int s = 0; s < Bn; s++) r += fmaxf(acc[s], 0.f);
    g_corr[b * HWn + p] = r * invn * (1.0f / Bn);
}

__global__ void cormap_kernel()
{
    __shared__ float smn[HWn], smx[HWn];
    const int b = blockIdx.x, p = threadIdx.x;
    const float v = g_corr[b * HWn + p];
    smn[p] = v; smx[p] = v;
    __syncthreads();
    for (int st = 512; st > 0; st >>= 1) {
        if (p < st && p + st < HWn) {
            smn[p] = fminf(smn[p], smn[p + st]);
            smx[p] = fmaxf(smx[p], smx[p + st]);
        }
        __syncthreads();
    }
    g_cormap[b * HWn + p] = (v - smn[0]) / (smx[0] - smn[0] + 1e-12f);
}

__global__ void proto_kernel(const float* __restrict__ x5n,
                             float* __restrict__ o_pro)
{
    __shared__ float sred[256];
    const int c = blockIdx.x, t = threadIdx.x;
    float s = 0.f;
    for (int n = t; n < NTOT; n += 256) {
        int b = n / HWn, p = n - b * HWn;
        s += x5n[(size_t)b * CMn + (size_t)c * HWn + p] * g_cormap[n];
    }
    sred[t] = s;
    __syncthreads();
    for (int st = 128; st > 0; st >>= 1) {
        if (t < st) sred[t] += sred[t + st];
        __syncthreads();
    }
    if (t == 0) {
        float v = sred[0] * (1.0f / NTOT);
        g_proto[c] = v;
        o_pro[c] = v;
    }
}

__global__ void out3_kernel(const float* __restrict__ x5n,
                            float* __restrict__ o3)
{
    const int i = blockIdx.x * 256 + threadIdx.x;
    const int b = i / CMn;
    const int r = i - b * CMn;
    const int c = r / HWn;
    const int p = r - c * HWn;
    o3[i] = x5n[i] * (g_proto[c] + g_cormap[b * HWn + p]);
}

// ---------------------------------------------------------------
extern "C" void kernel_launch(void* const* d_in, const int* in_sizes, int n_in,
                              void* d_out, int out_size)
{
    const float* x5    = (const float*)d_in[0];
    const float* convw = (const float*)d_in[1];
    const float* convb = (const float*)d_in[2];
    const float* qw    = (const float*)d_in[3];
    const float* qb    = (const float*)d_in[4];
    const float* kw    = (const float*)d_in[5];
    const float* kb    = (const float*)d_in[6];

    float* out    = (float*)d_out;
    float* o_x5   = out;
    float* o_pro  = out + (size_t)Bn * CMn;
    float* o_3    = o_pro + Cn;
    float* o_mask = o_3 + (size_t)Bn * CMn;

    dim3 cgrid(NTOT / 128, Cn / 128);   // (72, 4)

    conv_tc<0><<<cgrid, 256>>>(convw, x5,   convb, o_x5);   // x5new (split tf32)
    conv_tc<1><<<cgrid, 256>>>(qw,    o_x5, qb,    nullptr);// -> g_qh bf16 [n][c]
    conv_tc<2><<<cgrid, 256>>>(kw,    o_x5, kb,    nullptr);// -> g_kh bf16 [n][c]

    scores_bf<<<dim3(NTOT / 128, NTOT / 128), 256>>>();     // bf16 m16n8k16

    xw_mask_kernel<<<Bn, HWn>>>(o_mask);
    invnrm_kernel<<<144, dim3(64, 4)>>>(o_x5);
    seeds_kernel<<<Bn, Cn>>>(o_x5, o_mask);
    corr_kernel<<<dim3(Bn, 9), 64>>>(o_x5);
    cormap_kernel<<<Bn, HWn>>>();
    proto_kernel<<<Cn, 256>>>(o_x5, o_pro);
    out3_kernel<<<(Bn * CMn) / 256, 256>>>(o_x5, o_3);
}

// round 7
// speedup vs baseline: 4.5374x; 1.0511x over previous
#include <cuda_runtime.h>
#include <cuda_bf16.h>
#include <math.h>
#include <stdint.h>

#define Bn   16
#define Cn   512
#define HWn  576
#define CMn  (Cn*HWn)     // 294912
#define NTOT (Bn*HWn)     // 9216
#define NH   144          // 64-col half-tiles per row (9216/64)

// ---------------- device scratch (no allocs allowed) ----------------
__device__ __nv_bfloat16 g_qh[(size_t)NTOT*Cn];  // q, [n][c] bf16 transposed
__device__ __nv_bfloat16 g_kh[(size_t)NTOT*Cn];  // k, [n][c] bf16 transposed
__device__ float g_part[NTOT*NH];
__device__ float g_invnrm[NTOT];
__device__ float g_seeds[Bn*Cn];
__device__ float g_corr[NTOT];
__device__ float g_cormap[NTOT];
__device__ float g_proto[Cn];

__device__ __forceinline__ void cp16(uint32_t dst, const void* src) {
    asm volatile("cp.async.cg.shared.global [%0], [%1], 16;\n"
                 :: "r"(dst), "l"(src));
}
__device__ __forceinline__ uint32_t tf32r(float x) {
    uint32_t u;
    asm("cvt.rna.tf32.f32 %0, %1;" : "=r"(u) : "f"(x));
    return u;
}

#define KC   16
#define LDT  136
#define LDW  20

// ---------------------------------------------------------------
// Tensor-core conv GEMM (unchanged from R5).
// MODE 0: split tf32 (3 passes) + residual -> Yp fp32 (x5new).
// MODE 1/2: single tf32 pass -> g_qh / g_kh, bf16, transposed [n][c].
// ---------------------------------------------------------------
template<int MODE>
__global__ void __launch_bounds__(256) conv_tc(const float* __restrict__ Wm,
                                               const float* __restrict__ Xin,
                                               const float* __restrict__ bias,
                                               float* __restrict__ Yp)
{
    __shared__ __align__(16) float Ws[2][128][LDW];
    __shared__ __align__(16) float Xs[2][KC][LDT];

    const int t    = threadIdx.x;
    const int warp = t >> 5;
    const int lane = t & 31;
    const int wm   = (warp & 1) * 64;
    const int wn   = (warp >> 1) * 32;
    const int lr   = lane >> 2;
    const int lc   = lane & 3;
    const int N0   = blockIdx.x * 128;
    const int O0   = blockIdx.y * 128;

    const float* wsrc[2];
    const float* xsrc[2];
    uint32_t wdst[2], xdst[2];
    #pragma unroll
    for (int i = 0; i < 2; i++) {
        const int idx = t + i * 256;
        const int ow = idx >> 2;
        const int cv = (idx & 3) * 4;
        wsrc[i] = Wm + (size_t)(O0 + ow) * Cn + cv;
        wdst[i] = (uint32_t)__cvta_generic_to_shared(&Ws[0][ow][cv]);
        const int cl = idx >> 5;
        const int n4 = (idx & 31) * 4;
        const int col = N0 + n4;
        xsrc[i] = Xin + (size_t)(col / HWn) * CMn + (size_t)cl * HWn + (col % HWn);
        xdst[i] = (uint32_t)__cvta_generic_to_shared(&Xs[0][cl][n4]);
    }
    const uint32_t wstB = (uint32_t)(128 * LDW * sizeof(float));
    const uint32_t xstB = (uint32_t)(KC * LDT * sizeof(float));

    float d[4][4][4];
    #pragma unroll
    for (int mi = 0; mi < 4; mi++)
        #pragma unroll
        for (int ni = 0; ni < 4; ni++)
            #pragma unroll
            for (int r = 0; r < 4; r++) d[mi][ni][r] = 0.f;

    #pragma unroll
    for (int i = 0; i < 2; i++) {
        cp16(wdst[i], wsrc[i]);
        cp16(xdst[i], xsrc[i]);
    }
    asm volatile("cp.async.commit_group;\n" ::: "memory");

    const int NCH = Cn / KC;
    for (int cc = 0; cc < NCH; cc++) {
        if (cc + 1 < NCH) {
            const int s1 = (cc + 1) & 1;
            const int kof = (cc + 1) * KC;
            #pragma unroll
            for (int i = 0; i < 2; i++) {
                cp16(wdst[i] + s1 * wstB, wsrc[i] + kof);
                cp16(xdst[i] + s1 * xstB, xsrc[i] + (size_t)kof * HWn);
            }
        }
        asm volatile("cp.async.commit_group;\n" ::: "memory");
        asm volatile("cp.async.wait_group 1;\n" ::: "memory");
        __syncthreads();

        const int st = cc & 1;
        #pragma unroll
        for (int kf = 0; kf < 2; kf++) {
            const int k0 = kf * 8;
            uint32_t ah[4][4], al[4][4];
            #pragma unroll
            for (int mi = 0; mi < 4; mi++) {
                float f0 = Ws[st][wm + mi * 16 + lr    ][k0 + lc    ];
                float f1 = Ws[st][wm + mi * 16 + 8 + lr][k0 + lc    ];
                float f2 = Ws[st][wm + mi * 16 + lr    ][k0 + lc + 4];
                float f3 = Ws[st][wm + mi * 16 + 8 + lr][k0 + lc + 4];
                ah[mi][0] = tf32r(f0); ah[mi][1] = tf32r(f1);
                ah[mi][2] = tf32r(f2); ah[mi][3] = tf32r(f3);
                if (MODE == 0) {
                    al[mi][0] = tf32r(f0 - __uint_as_float(ah[mi][0]));
                    al[mi][1] = tf32r(f1 - __uint_as_float(ah[mi][1]));
                    al[mi][2] = tf32r(f2 - __uint_as_float(ah[mi][2]));
                    al[mi][3] = tf32r(f3 - __uint_as_float(ah[mi][3]));
                }
            }
            #pragma unroll
            for (int ni = 0; ni < 4; ni++) {
                float g0 = Xs[st][k0 + lc    ][wn + ni * 8 + lr];
                float g1 = Xs[st][k0 + lc + 4][wn + ni * 8 + lr];
                uint32_t bh0 = tf32r(g0), bh1 = tf32r(g1);
                uint32_t bl0 = 0, bl1 = 0;
                if (MODE == 0) {
                    bl0 = tf32r(g0 - __uint_as_float(bh0));
                    bl1 = tf32r(g1 - __uint_as_float(bh1));
                }
                #pragma unroll
                for (int mi = 0; mi < 4; mi++) {
                    asm volatile(
                        "mma.sync.aligned.m16n8k8.row.col.f32.tf32.tf32.f32 "
                        "{%0,%1,%2,%3}, {%4,%5,%6,%7}, {%8,%9}, {%0,%1,%2,%3};"
                        : "+f"(d[mi][ni][0]), "+f"(d[mi][ni][1]),
                          "+f"(d[mi][ni][2]), "+f"(d[mi][ni][3])
                        : "r"(ah[mi][0]), "r"(ah[mi][1]), "r"(ah[mi][2]), "r"(ah[mi][3]),
                          "r"(bh0), "r"(bh1));
                    if (MODE == 0) {
                        asm volatile(
                            "mma.sync.aligned.m16n8k8.row.col.f32.tf32.tf32.f32 "
                            "{%0,%1,%2,%3}, {%4,%5,%6,%7}, {%8,%9}, {%0,%1,%2,%3};"
                            : "+f"(d[mi][ni][0]), "+f"(d[mi][ni][1]),
                              "+f"(d[mi][ni][2]), "+f"(d[mi][ni][3])
                            : "r"(ah[mi][0]), "r"(ah[mi][1]), "r"(ah[mi][2]), "r"(ah[mi][3]),
                              "r"(bl0), "r"(bl1));
                        asm volatile(
                            "mma.sync.aligned.m16n8k8.row.col.f32.tf32.tf32.f32 "
                            "{%0,%1,%2,%3}, {%4,%5,%6,%7}, {%8,%9}, {%0,%1,%2,%3};"
                            : "+f"(d[mi][ni][0]), "+f"(d[mi][ni][1]),
                              "+f"(d[mi][ni][2]), "+f"(d[mi][ni][3])
                            : "r"(al[mi][0]), "r"(al[mi][1]), "r"(al[mi][2]), "r"(al[mi][3]),
                              "r"(bh0), "r"(bh1));
                    }
                }
            }
        }
        __syncthreads();
    }

    #pragma unroll
    for (int mi = 0; mi < 4; mi++) {
        const int row0 = O0 + wm + mi * 16 + lr;
        const float b0 = bias[row0];
        const float b1 = bias[row0 + 8];
        #pragma unroll
        for (int ni = 0; ni < 4; ni++) {
            const int col = N0 + wn + ni * 8 + 2 * lc;
            if (MODE == 0) {
                const int bb = col / HWn;
                const int m  = col - bb * HWn;
                float2 v0, v1;
                v0.x = d[mi][ni][0] + b0; v0.y = d[mi][ni][1] + b0;
                v1.x = d[mi][ni][2] + b1; v1.y = d[mi][ni][3] + b1;
                const float* x0 = Xin + (size_t)bb * CMn + (size_t)row0 * HWn + m;
                float2 r0 = *(const float2*)x0;
                float2 r1 = *(const float2*)(x0 + 8 * HWn);
                v0.x += r0.x; v0.y += r0.y;
                v1.x += r1.x; v1.y += r1.y;
                float* y0 = Yp + (size_t)bb * CMn + (size_t)row0 * HWn + m;
                *(float2*)y0 = v0;
                *(float2*)(y0 + 8 * HWn) = v1;
            } else {
                __nv_bfloat16* Yh = (MODE == 1) ? g_qh : g_kh;
                Yh[(size_t)col       * Cn + row0    ] = __float2bfloat16(d[mi][ni][0] + b0);
                Yh[(size_t)(col + 1) * Cn + row0    ] = __float2bfloat16(d[mi][ni][1] + b0);
                Yh[(size_t)col       * Cn + row0 + 8] = __float2bfloat16(d[mi][ni][2] + b1);
                Yh[(size_t)(col + 1) * Cn + row0 + 8] = __float2bfloat16(d[mi][ni][3] + b1);
            }
        }
    }
}

// ---------------------------------------------------------------
// bf16 scores GEMM v2 (FIXED cp.async layout): 128x128 tile, m16n8k16,
// ldmatrix fragments, K=32 per barrier, 4-stage pipeline (lookahead 2).
// Each thread copies the contiguous 32B half [cseg*32, cseg*32+32) of
// its row's 64B k-run (two adjacent 16B cp.async).
// ---------------------------------------------------------------
#define KC2   32                       // k per chunk
#define LDQ2  40                       // bf16 per smem row (32 + 8 pad)
#define TILEB (128 * LDQ2 * 2)         // 10240 B per tile-stage
#define SMEMB (8 * TILEB)              // 81920 B total

__global__ void __launch_bounds__(256) scores_bf2()
{
    extern __shared__ __align__(16) char sm[];
    __nv_bfloat16* Qb0 = (__nv_bfloat16*)sm;              // 4 stages
    __nv_bfloat16* Kb0 = (__nv_bfloat16*)(sm + 4 * TILEB);// 4 stages
    float (*red)[4] = (float(*)[4])sm;                    // aliased after loop

    const int t    = threadIdx.x;
    const int warp = t >> 5;
    const int lane = t & 31;
    const int wm   = (warp & 1) * 64;
    const int wn   = (warp >> 1) * 32;
    const int lr   = lane >> 2;
    const int lc   = lane & 3;
    const int R0   = blockIdx.x * 128;
    const int N0   = blockIdx.y * 128;

    // cp.async: thread (t) -> row t>>1, 32-byte half (t&1) of the 64B k-run
    const int crow = t >> 1;            // 0..127
    const int cseg = t & 1;             // 0 or 1
    const __nv_bfloat16* qsrc = g_qh + (size_t)(R0 + crow) * Cn + cseg * 16;
    const __nv_bfloat16* ksrc = g_kh + (size_t)(N0 + crow) * Cn + cseg * 16;
    const uint32_t qd0 = (uint32_t)__cvta_generic_to_shared(Qb0)
                       + crow * (LDQ2 * 2) + cseg * 32;
    const uint32_t kd0 = (uint32_t)__cvta_generic_to_shared(Kb0)
                       + crow * (LDQ2 * 2) + cseg * 32;

    // ldmatrix per-lane addressing
    const int lrow = lane & 15;
    const int loff = (lane >> 4) * 16;  // byte offset within 32B k-run half
    const uint32_t qa0 = (uint32_t)__cvta_generic_to_shared(Qb0)
                       + (wm + lrow) * (LDQ2 * 2) + loff;
    const uint32_t ka0 = (uint32_t)__cvta_generic_to_shared(Kb0)
                       + (wn + lrow) * (LDQ2 * 2) + loff;

    float d[4][4][4];
    #pragma unroll
    for (int mi = 0; mi < 4; mi++)
        #pragma unroll
        for (int ni = 0; ni < 4; ni++)
            #pragma unroll
            for (int r = 0; r < 4; r++) d[mi][ni][r] = 0.f;

    const int NCH = Cn / KC2;   // 16 chunks

    // prologue: chunks 0,1 -> stages 0,1
    #pragma unroll
    for (int s = 0; s < 2; s++) {
        cp16(qd0 + s * TILEB,      qsrc + s * KC2);
        cp16(qd0 + s * TILEB + 16, qsrc + s * KC2 + 8);
        cp16(kd0 + s * TILEB,      ksrc + s * KC2);
        cp16(kd0 + s * TILEB + 16, ksrc + s * KC2 + 8);
        asm volatile("cp.async.commit_group;\n" ::: "memory");
    }

    for (int cc = 0; cc < NCH; cc++) {
        if (cc + 2 < NCH) {
            const uint32_t so = ((cc + 2) & 3) * TILEB;
            const int go = (cc + 2) * KC2;
            cp16(qd0 + so,      qsrc + go);
            cp16(qd0 + so + 16, qsrc + go + 8);
            cp16(kd0 + so,      ksrc + go);
            cp16(kd0 + so + 16, ksrc + go + 8);
        }
        asm volatile("cp.async.commit_group;\n" ::: "memory");
        asm volatile("cp.async.wait_group 2;\n" ::: "memory");
        __syncthreads();

        const uint32_t stO = (cc & 3) * TILEB;
        #pragma unroll
        for (int kf = 0; kf < 2; kf++) {
            const uint32_t ko = kf * 32;   // bytes: 16 bf16 per k-run
            uint32_t a[4][4];
            #pragma unroll
            for (int mi = 0; mi < 4; mi++)
                asm volatile(
                    "ldmatrix.sync.aligned.m8n8.x4.shared.b16 {%0,%1,%2,%3}, [%4];"
                    : "=r"(a[mi][0]), "=r"(a[mi][1]), "=r"(a[mi][2]), "=r"(a[mi][3])
                    : "r"(qa0 + stO + ko + mi * 16 * (LDQ2 * 2)));
            uint32_t b[4][2];
            #pragma unroll
            for (int nj = 0; nj < 2; nj++)
                asm volatile(
                    "ldmatrix.sync.aligned.m8n8.x4.shared.b16 {%0,%1,%2,%3}, [%4];"
                    : "=r"(b[nj*2][0]), "=r"(b[nj*2+1][0]),
                      "=r"(b[nj*2][1]), "=r"(b[nj*2+1][1])
                    : "r"(ka0 + stO + ko + nj * 16 * (LDQ2 * 2)));
            #pragma unroll
            for (int mi = 0; mi < 4; mi++)
                #pragma unroll
                for (int ni = 0; ni < 4; ni++)
                    asm volatile(
                        "mma.sync.aligned.m16n8k16.row.col.f32.bf16.bf16.f32 "
                        "{%0,%1,%2,%3}, {%4,%5,%6,%7}, {%8,%9}, {%0,%1,%2,%3};"
                        : "+f"(d[mi][ni][0]), "+f"(d[mi][ni][1]),
                          "+f"(d[mi][ni][2]), "+f"(d[mi][ni][3])
                        : "r"(a[mi][0]), "r"(a[mi][1]), "r"(a[mi][2]), "r"(a[mi][3]),
                          "r"(b[ni][0]), "r"(b[ni][1]));
        }
    }
    __syncthreads();   // smem now dead -> safe to alias red

    #pragma unroll
    for (int mi = 0; mi < 4; mi++) {
        float ra = -1e30f, rb = -1e30f;
        #pragma unroll
        for (int ni = 0; ni < 4; ni++) {
            ra = fmaxf(ra, fmaxf(d[mi][ni][0], d[mi][ni][1]));
            rb = fmaxf(rb, fmaxf(d[mi][ni][2], d[mi][ni][3]));
        }
        ra = fmaxf(ra, __shfl_xor_sync(0xFFFFFFFFu, ra, 1));
        ra = fmaxf(ra, __shfl_xor_sync(0xFFFFFFFFu, ra, 2));
        rb = fmaxf(rb, __shfl_xor_sync(0xFFFFFFFFu, rb, 1));
        rb = fmaxf(rb, __shfl_xor_sync(0xFFFFFFFFu, rb, 2));
        if (lc == 0) {
            red[wm + mi * 16 + lr    ][warp >> 1] = ra;
            red[wm + mi * 16 + 8 + lr][warp >> 1] = rb;
        }
    }
    __syncthreads();

    if (t < 128) {
        const float h0 = fmaxf(red[t][0], red[t][1]);
        const float h1 = fmaxf(red[t][2], red[t][3]);
        const size_t r2 = R0 + t;
        g_part[r2 * NH + blockIdx.y * 2    ] = h0;
        g_part[r2 * NH + blockIdx.y * 2 + 1] = h1;
    }
}

// ---------------------------------------------------------------
__global__ void xw_mask_kernel(float* __restrict__ o_mask)
{
    __shared__ float smax[HWn];
    const int b = blockIdx.x, p = threadIdx.x;
    const float* gp = g_part + (size_t)(b * HWn + p) * NH;
    float s = 0.f;
    #pragma unroll
    for (int bk = 0; bk < Bn; bk++) {
        float m = gp[bk * 9];
        #pragma unroll
        for (int h = 1; h < 9; h++) m = fmaxf(m, gp[bk * 9 + h]);
        s += m;
    }
    smax[p] = s;
    __syncthreads();
    for (int st = 512; st > 0; st >>= 1) {
        if (p < st && p + st < HWn) smax[p] = fmaxf(smax[p], smax[p + st]);
        __syncthreads();
    }
    o_mask[b * HWn + p] = (s == smax[0]) ? 1.0f : 0.0f;
}

__global__ void invnrm_kernel(const float* __restrict__ x5n)
{
    __shared__ float part[4][64];
    const int b  = blockIdx.x / 9;
    const int p0 = (blockIdx.x % 9) * 64;
    const int px = threadIdx.x;
    const int cy = threadIdx.y;
    const float* xp = x5n + (size_t)b * CMn + p0 + px;
    float s = 0.f;
    for (int c = cy; c < Cn; c += 4) {
        float v = xp[(size_t)c * HWn];
        s += v * v;
    }
    part[cy][px] = s;
    __syncthreads();
    if (cy == 0) {
        float tot = part[0][px] + part[1][px] + part[2][px] + part[3][px];
        g_invnrm[b * HWn + p0 + px] = 1.0f / fmaxf(sqrtf(tot), 1e-12f);
    }
}

__global__ void seeds_kernel(const float* __restrict__ x5n,
                             const float* __restrict__ mask)
{
    __shared__ int cnt;
    __shared__ int plist[HWn];
    const int b = blockIdx.x, c = threadIdx.x;
    if (c == 0) cnt = 0;
    __syncthreads();
    for (int p = c; p < HWn; p += 512)
        if (mask[b * HWn + p] > 0.5f) {
            int i = atomicAdd(&cnt, 1);
            plist[i] = p;
        }
    __syncthreads();
    float s = 0.f;
    for (int i = 0; i < cnt; i++) {
        int p = plist[i];
        s += x5n[(size_t)b * CMn + (size_t)c * HWn + p] * g_invnrm[b * HWn + p];
    }
    g_seeds[b * Cn + c] = s;
}

__global__ void corr_kernel(const float* __restrict__ x5n)
{
    __shared__ __align__(16) float ssT[Cn][Bn];
    const int b = blockIdx.x;
    const int p = blockIdx.y * 64 + threadIdx.x;
    for (int i = threadIdx.x; i < Cn * Bn; i += 64) {
        int c = i >> 4, s = i & 15;
        ssT[c][s] = g_seeds[s * Cn + c];
    }
    __syncthreads();
    float acc[Bn] = {};
    const float invn = g_invnrm[b * HWn + p];
    const float* xp = x5n + (size_t)b * CMn + p;
    for (int c = 0; c < Cn; c++) {
        float x = xp[(size_t)c * HWn];
        #pragma unroll
        for (int s4 = 0; s4 < 4; s4++) {
            float4 sv = *(const float4*)&ssT[c][s4 * 4];
            acc[s4 * 4 + 0] += x * sv.x;
            acc[s4 * 4 + 1] += x * sv.y;
            acc[s4 * 4 + 2] += x * sv.z;
            acc[s4 * 4 + 3] += x * sv.w;
        }
    }
    float r = 0.f;
    #pragma unroll
    for (int s = 0; s < Bn; s++) r += fmaxf(acc[s], 0.f);
    g_corr[b * HWn + p] = r * invn * (1.0f / Bn);
}

__global__ void cormap_kernel()
{
    __shared__ float smn[HWn], smx[HWn];
    const int b = blockIdx.x, p = threadIdx.x;
    const float v = g_corr[b * HWn + p];
    smn[p] = v; smx[p] = v;
    __syncthreads();
    for (int st = 512; st > 0; st >>= 1) {
        if (p < st && p + st < HWn) {
            smn[p] = fminf(smn[p], smn[p + st]);
            smx[p] = fmaxf(smx[p], smx[p + st]);
        }
        __syncthreads();
    }
    g_cormap[b * HWn + p] = (v - smn[0]) / (smx[0] - smn[0] + 1e-12f);
}

__global__ void proto_kernel(const float* __restrict__ x5n,
                             float* __restrict__ o_pro)
{
    __shared__ float sred[256];
    const int c = blockIdx.x, t = threadIdx.x;
    float s = 0.f;
    for (int n = t; n < NTOT; n += 256) {
        int b = n / HWn, p = n - b * HWn;
        s += x5n[(size_t)b * CMn + (size_t)c * HWn + p] * g_cormap[n];
    }
    sred[t] = s;
    __syncthreads();
    for (int st = 128; st > 0; st >>= 1) {
        if (t < st) sred[t] += sred[t + st];
        __syncthreads();
    }
    if (t == 0) {
        float v = sred[0] * (1.0f / NTOT);
        g_proto[c] = v;
        o_pro[c] = v;
    }
}

__global__ void out3_kernel(const float* __restrict__ x5n,
                            float* __restrict__ o3)
{
    const int i = blockIdx.x * 256 + threadIdx.x;
    const int b = i / CMn;
    const int r = i - b * CMn;
    const int c = r / HWn;
    const int p = r - c * HWn;
    o3[i] = x5n[i] * (g_proto[c] + g_cormap[b * HWn + p]);
}

// ---------------------------------------------------------------
extern "C" void kernel_launch(void* const* d_in, const int* in_sizes, int n_in,
                              void* d_out, int out_size)
{
    const float* x5    = (const float*)d_in[0];
    const float* convw = (const float*)d_in[1];
    const float* convb = (const float*)d_in[2];
    const float* qw    = (const float*)d_in[3];
    const float* qb    = (const float*)d_in[4];
    const float* kw    = (const float*)d_in[5];
    const float* kb    = (const float*)d_in[6];

    float* out    = (float*)d_out;
    float* o_x5   = out;
    float* o_pro  = out + (size_t)Bn * CMn;
    float* o_3    = o_pro + Cn;
    float* o_mask = o_3 + (size_t)Bn * CMn;

    static bool attr_set = false;
    if (!attr_set) {
        cudaFuncSetAttribute(scores_bf2,
                             cudaFuncAttributeMaxDynamicSharedMemorySize, SMEMB);
        attr_set = true;
    }

    dim3 cgrid(NTOT / 128, Cn / 128);

    conv_tc<0><<<cgrid, 256>>>(convw, x5,   convb, o_x5);
    conv_tc<1><<<cgrid, 256>>>(qw,    o_x5, qb,    nullptr);
    conv_tc<2><<<cgrid, 256>>>(kw,    o_x5, kb,    nullptr);

    scores_bf2<<<dim3(NTOT / 128, NTOT / 128), 256, SMEMB>>>();

    xw_mask_kernel<<<Bn, HWn>>>(o_mask);
    invnrm_kernel<<<144, dim3(64, 4)>>>(o_x5);
    seeds_kernel<<<Bn, Cn>>>(o_x5, o_mask);
    corr_kernel<<<dim3(Bn, 9), 64>>>(o_x5);
    cormap_kernel<<<Bn, HWn>>>();
    proto_kernel<<<Cn, 256>>>(o_x5, o_pro);
    out3_kernel<<<(Bn * CMn) / 256, 256>>>(o_x5, o_3);
}